// round 7
// baseline (speedup 1.0000x reference)
#include <cuda_runtime.h>
#include <cuda_bf16.h>
#include <cuda_fp16.h>
#include <cstdint>
#include <cstddef>

#define N_NODES 1024
#define F_IN    32
#define HID     64
#define OUT     32
#define I_TILE  8
#define J_TILE  16
#define JITERS  8     // j-tiles per block

#if defined(__CUDA_ARCH__) && (defined(__CUDA_ARCH_FEAT_SM103_ALL) || \
                               defined(__CUDA_ARCH_FEAT_SM100_ALL) || \
                               defined(__CUDA_ARCH_FAMILY_SPECIFIC__))
#define USE_TC 1
#else
#define USE_TC 0
#endif

__device__ float g_A[N_NODES * HID];   // A[i,h] = Emb[i,:] . W1[h, :F]
__device__ float g_B[N_NODES * HID];   // B[j,h] = Emb[j,:] . W1[h, F:]

// ---------------------------------------------------------------------------
// Kernel 1: A/B precompute (tiny)
// ---------------------------------------------------------------------------
__global__ void precompute_AB(const float* __restrict__ Emb,
                              const float* __restrict__ W1) {
    int idx = blockIdx.x * blockDim.x + threadIdx.x;
    int i = idx >> 6;
    int h = idx & 63;
    const float* er = Emb + i * F_IN;
    const float* wr = W1 + h * (2 * F_IN);
    float sa = 0.f, sb = 0.f;
#pragma unroll
    for (int f = 0; f < F_IN; ++f) {
        float e = er[f];
        sa = fmaf(e, wr[f], sa);
        sb = fmaf(e, wr[F_IN + f], sb);
    }
    g_A[idx] = sa;
    g_B[idx] = sb;
}

// ---------------------------------------------------------------------------
// Helpers
// ---------------------------------------------------------------------------
__device__ __forceinline__ unsigned smem_u32(const void* p) {
    unsigned a;
    asm("{ .reg .u64 t; cvta.to.shared.u64 t, %1; cvt.u32.u64 %0, t; }"
        : "=r"(a) : "l"(p));
    return a;
}

__device__ __forceinline__ unsigned long long pack2(float lo, float hi) {
    unsigned long long r;
    asm("mov.b64 %0, {%1, %2};"
        : "=l"(r) : "r"(__float_as_uint(lo)), "r"(__float_as_uint(hi)));
    return r;
}

__device__ __forceinline__ void unpack2(unsigned long long v, float& lo, float& hi) {
    unsigned a, b;
    asm("mov.b64 {%0, %1}, %2;" : "=r"(a), "=r"(b) : "l"(v));
    lo = __uint_as_float(a);
    hi = __uint_as_float(b);
}

__device__ __forceinline__ unsigned long long lds_u64(unsigned addr) {
    unsigned long long r;
    asm volatile("ld.shared.b64 %0, [%1];" : "=l"(r) : "r"(addr));
    return r;
}

#define FFMA2(acc, a, b) \
    asm("fma.rn.f32x2 %0, %1, %2, %0;" : "+l"(acc) : "l"(a), "l"(b))

__device__ __forceinline__ float swish_fast(float x) {
    float e;
    asm("ex2.approx.f32 %0, %1;" : "=f"(e) : "f"(x * (-1.442695040888963f)));
    float r;
    asm("rcp.approx.f32 %0, %1;" : "=f"(r) : "f"(1.0f + e));
    return x * r;
}

// pack two f32 -> f16x2 (first arg -> low half)
__device__ __forceinline__ unsigned cvt2f16(float lo, float hi) {
    unsigned r;
    asm("cvt.rn.f16x2.f32 %0, %1, %2;" : "=r"(r) : "f"(hi), "f"(lo));
    return r;
}

#if USE_TC
__device__ __forceinline__ bool elect_one() {
    unsigned pred;
    asm volatile("{\n\t.reg .pred p;\n\telect.sync _|p, 0xFFFFFFFF;\n\t"
                 "selp.b32 %0, 1, 0, p;\n\t}" : "=r"(pred));
    return pred != 0;
}

__device__ __forceinline__ void mbar_init(unsigned addr, unsigned cnt) {
    asm volatile("mbarrier.init.shared.b64 [%0], %1;" :: "r"(addr), "r"(cnt) : "memory");
}

__device__ __forceinline__ void mbar_inval(unsigned addr) {
    asm volatile("mbarrier.inval.shared.b64 [%0];" :: "r"(addr) : "memory");
}

__device__ __forceinline__ void mbar_wait(unsigned addr, unsigned parity) {
    asm volatile(
        "{\n\t.reg .pred P;\n\t"
        "WL_%=:\n\t"
        "mbarrier.try_wait.parity.acquire.cta.shared::cta.b64 P, [%0], %1, 0x989680;\n\t"
        "@P bra.uni WD_%=;\n\t"
        "bra.uni WL_%=;\n\t"
        "WD_%=:\n\t}"
        :: "r"(addr), "r"(parity) : "memory");
}

// SW128 K-major smem descriptor: layout=2, version=1, SBO=64, LBO=1
__device__ __forceinline__ unsigned long long sdesc(unsigned addr) {
    const unsigned long long base =
        (2ull << 61) | (1ull << 46) | (64ull << 32) | (1ull << 16);
    return base | ((unsigned long long)(addr >> 4) & 0x3FFF);
}

// idesc kind::f16: dtype=F32, atype=btype=F16(0), N=32, M=128 -> 0x8080010
#define MMA_IDESC ((1u << 4) | ((OUT / 8) << 17) | (8u << 24))

// TS-form: A operand in TMEM
__device__ __forceinline__ void mma_f16_ts(unsigned d_tmem, unsigned a_tmem,
                                           unsigned long long b_desc,
                                           unsigned en) {
    asm volatile(
        "{\n\t.reg .pred p;\n\t"
        "setp.ne.u32 p, %5, 0;\n\t"
        "tcgen05.mma.cta_group::1.kind::f16 [%0], [%1], %2, %3, {%4, %4, %4, %4}, p;\n\t"
        "}"
        :: "r"(d_tmem), "r"(a_tmem), "l"(b_desc), "r"(MMA_IDESC), "r"(0u), "r"(en)
        : "memory");
}
#endif  // USE_TC

// ---------------------------------------------------------------------------
// Dynamic SMEM layout. Total 15744 B.
// ---------------------------------------------------------------------------
#define SM_TMEM  0
#define SM_MBAR0 8
#define SM_MBAR1 16
#define SM_WHI   1024                     // 32 x 64 f16 SW128 = 4KB
#define SM_WLO   (SM_WHI + 4096)          // 5120
#define SM_BS    (SM_WLO + 4096)          // 9216 (16 rows x 64 f, XOR layout)
#define SM_AS    (SM_BS + 4096)           // 13312 (8 rows x 64 f = 2KB)
#define SM_B1    (SM_AS + 2048)           // 15360
#define SM_B2    (SM_B1 + 256)            // 15616
#define SM_TOTAL (SM_B2 + 128)            // 15744

// Fallback layout (front of same buffer)
#define FB_W2P  0
#define FB_B1   (FB_W2P + HID * 16 * 8)
#define FB_B2   (FB_B1 + HID * 4)

#define SWZ(off) ((off) ^ (((off) >> 3) & 0x70))
// Bs addressing: row jl (256B), float4 slot c4 stored at (c4 ^ jl)*16
#define BS_ADDR(jl, c4) (SM_BS + ((jl) << 8) + ((unsigned)((c4) ^ (jl)) << 4))

// TMEM column offsets (alloc 128 cols)
#define TM_D0 0
#define TM_D1 32
#define TM_A0 64
#define TM_A1 96

// ---------------------------------------------------------------------------
// Kernel 2: fused edge MLP; h1 goes regs -> TMEM (tcgen05.st) -> TS-mode MMA.
// Block = 128 thr; per iter: tile 8 i x 16 j (M=128), N=32, K=64.
// ---------------------------------------------------------------------------
__global__ __launch_bounds__(128)
void edge_mlp_tc(const float* __restrict__ Edges,
                 const float* __restrict__ Coords,
                 const float* __restrict__ b1,
                 const float* __restrict__ W2,
                 const float* __restrict__ b2,
                 float* __restrict__ out) {
    extern __shared__ char smem[];
    const int tid  = threadIdx.x;
    const int warp = tid >> 5;
    const int ibase = blockIdx.y * I_TILE;
    const int jblk  = blockIdx.x * (J_TILE * JITERS);

    const int i  = ibase + (tid >> 4);
    const int jl = tid & 15;

    const float cx = Coords[i * 3 + 0];
    const float cy = Coords[i * 3 + 1];
    const float cz = Coords[i * 3 + 2];

#if USE_TC
    const unsigned sb = smem_u32(smem);
    if (warp == 0) {
        asm volatile("tcgen05.alloc.cta_group::1.sync.aligned.shared::cta.b32 [%0], %1;"
                     :: "r"(sb + SM_TMEM), "r"(128u) : "memory");
        asm volatile("tcgen05.relinquish_alloc_permit.cta_group::1.sync.aligned;");
    }
    if (tid == 0) {
        mbar_init(sb + SM_MBAR0, 1);
        mbar_init(sb + SM_MBAR1, 1);
    }

    // ---- stage W2 (fp16 hi/lo, SW128), A i-rows, b1, b2 — once per block ----
    for (int p = tid; p < OUT * 32; p += 128) {
        int o = p >> 5, h2 = p & 31;
        float w0 = W2[o * HID + 2 * h2];
        float w1 = W2[o * HID + 2 * h2 + 1];
        unsigned hi = cvt2f16(w0, w1);
        float r0 = w0 - __half2float(__ushort_as_half((unsigned short)(hi & 0xFFFF)));
        float r1 = w1 - __half2float(__ushort_as_half((unsigned short)(hi >> 16)));
        unsigned lo = cvt2f16(r0, r1);
        unsigned sw = SWZ((unsigned)(o * 128 + h2 * 4));
        *(unsigned*)(smem + SM_WHI + sw) = hi;
        *(unsigned*)(smem + SM_WLO + sw) = lo;
    }
    {
        const float4* src = (const float4*)(g_A + ibase * HID);
        for (int p = tid; p < 128; p += 128)
            ((float4*)(smem + SM_AS))[p] = src[p];
        if (tid < 16) ((float4*)(smem + SM_B1))[tid] = ((const float4*)b1)[tid];
        else if (tid < 24) ((float4*)(smem + SM_B2))[tid - 16] = ((const float4*)b2)[tid - 16];
    }
    asm volatile("fence.proxy.async.shared::cta;" ::: "memory");
    __syncthreads();

    unsigned tmem;
    asm("ld.shared.b32 %0, [%1];" : "=r"(tmem) : "r"(sb + SM_TMEM));

    const unsigned long long whiD = sdesc(sb + SM_WHI);
    const unsigned long long wloD = sdesc(sb + SM_WLO);
    const unsigned warp_off = (unsigned)warp << 21;

    const float4* Asr = (const float4*)(smem + SM_AS + (tid >> 4) * 256);
    const float4* b1s = (const float4*)(smem + SM_B1);
    const float4* b2s = (const float4*)(smem + SM_B2);

    size_t orow_prev = 0;

    for (int t = 0; t < JITERS; ++t) {
        const int jbase = jblk + t * J_TILE;

        // ---- stage B j-tile (coalesced, XOR layout) ----
        {
            const float4* src = (const float4*)(g_B + jbase * HID);
#pragma unroll
            for (int p = tid; p < 256; p += 128) {
                int jj = p >> 4, c4 = p & 15;
                *(float4*)(smem + BS_ADDR(jj, c4)) = src[p];
            }
        }
        __syncthreads();

        const int j = jbase + jl;
        float dx = cx - Coords[j * 3 + 0];
        float dy = cy - Coords[j * 3 + 1];
        float dz = cz - Coords[j * 3 + 2];
        float d2 = dx * dx + dy * dy + dz * dz;
        float dist = (d2 > 0.f) ? d2 * rsqrtf(d2) : 0.f;
        const float w = Edges[(size_t)i * N_NODES + j] * dist;

        // ---- h1 = swish(w*(A+B)+b1) -> 32 f16x2 regs ----
        unsigned v[32];
#pragma unroll
        for (int c = 0; c < 8; ++c) {
            float4 a0 = Asr[2 * c];
            float4 a1 = Asr[2 * c + 1];
            float4 p0 = *(const float4*)(smem + BS_ADDR(jl, 2 * c));
            float4 p1 = *(const float4*)(smem + BS_ADDR(jl, 2 * c + 1));
            float4 q0 = b1s[2 * c];
            float4 q1 = b1s[2 * c + 1];

            float g0 = swish_fast(fmaf(w, a0.x + p0.x, q0.x));
            float g1 = swish_fast(fmaf(w, a0.y + p0.y, q0.y));
            float g2 = swish_fast(fmaf(w, a0.z + p0.z, q0.z));
            float g3 = swish_fast(fmaf(w, a0.w + p0.w, q0.w));
            float g4 = swish_fast(fmaf(w, a1.x + p1.x, q1.x));
            float g5 = swish_fast(fmaf(w, a1.y + p1.y, q1.y));
            float g6 = swish_fast(fmaf(w, a1.z + p1.z, q1.z));
            float g7 = swish_fast(fmaf(w, a1.w + p1.w, q1.w));

            v[4 * c + 0] = cvt2f16(g0, g1);
            v[4 * c + 1] = cvt2f16(g2, g3);
            v[4 * c + 2] = cvt2f16(g4, g5);
            v[4 * c + 3] = cvt2f16(g6, g7);
        }

        // ---- store h1 to TMEM A buffer (warp-collective) ----
        const unsigned atm = tmem + ((t & 1) ? TM_A1 : TM_A0);
        asm volatile(
            "tcgen05.st.sync.aligned.32x32b.x32.b32 [%0], "
            "{%1, %2, %3, %4, %5, %6, %7, %8, "
            " %9, %10, %11, %12, %13, %14, %15, %16, "
            " %17, %18, %19, %20, %21, %22, %23, %24, "
            " %25, %26, %27, %28, %29, %30, %31, %32};"
            :: "r"(atm + warp_off),
               "r"(v[0]),  "r"(v[1]),  "r"(v[2]),  "r"(v[3]),
               "r"(v[4]),  "r"(v[5]),  "r"(v[6]),  "r"(v[7]),
               "r"(v[8]),  "r"(v[9]),  "r"(v[10]), "r"(v[11]),
               "r"(v[12]), "r"(v[13]), "r"(v[14]), "r"(v[15]),
               "r"(v[16]), "r"(v[17]), "r"(v[18]), "r"(v[19]),
               "r"(v[20]), "r"(v[21]), "r"(v[22]), "r"(v[23]),
               "r"(v[24]), "r"(v[25]), "r"(v[26]), "r"(v[27]),
               "r"(v[28]), "r"(v[29]), "r"(v[30]), "r"(v[31])
            : "memory");
        asm volatile("tcgen05.wait::st.sync.aligned;" ::: "memory");
        asm volatile("tcgen05.fence::before_thread_sync;" ::: "memory");
        __syncthreads();

        // ---- issue MMA[t] (TS form): D[t%2] = A_tmem * (Whi + Wlo) ----
        if (warp == 0 && elect_one()) {
            asm volatile("tcgen05.fence::after_thread_sync;" ::: "memory");
            const unsigned dtm = tmem + ((t & 1) ? TM_D1 : TM_D0);
            unsigned en = 0;
#pragma unroll
            for (int k = 0; k < 4; ++k) { mma_f16_ts(dtm, atm + k * 8, whiD + 2 * k, en); en = 1; }
#pragma unroll
            for (int k = 0; k < 4; ++k) { mma_f16_ts(dtm, atm + k * 8, wloD + 2 * k, 1); }
            asm volatile(
                "tcgen05.commit.cta_group::1.mbarrier::arrive::one.shared::cluster.b64 [%0];"
                :: "r"(sb + SM_MBAR0 + (unsigned)(t & 1) * 8) : "memory");
        }

        // ---- epilogue of tile t-1 (overlaps MMA[t]) ----
        if (t > 0) {
            const int tp = t - 1;
            mbar_wait(sb + SM_MBAR0 + (unsigned)(tp & 1) * 8, (tp >> 1) & 1);
            asm volatile("tcgen05.fence::after_thread_sync;" ::: "memory");

            unsigned d[32];
            asm volatile(
                "tcgen05.ld.sync.aligned.32x32b.x32.b32 "
                "{%0, %1, %2, %3, %4, %5, %6, %7, "
                " %8, %9, %10, %11, %12, %13, %14, %15, "
                " %16, %17, %18, %19, %20, %21, %22, %23, "
                " %24, %25, %26, %27, %28, %29, %30, %31}, [%32];"
                : "=r"(d[0]),  "=r"(d[1]),  "=r"(d[2]),  "=r"(d[3]),
                  "=r"(d[4]),  "=r"(d[5]),  "=r"(d[6]),  "=r"(d[7]),
                  "=r"(d[8]),  "=r"(d[9]),  "=r"(d[10]), "=r"(d[11]),
                  "=r"(d[12]), "=r"(d[13]), "=r"(d[14]), "=r"(d[15]),
                  "=r"(d[16]), "=r"(d[17]), "=r"(d[18]), "=r"(d[19]),
                  "=r"(d[20]), "=r"(d[21]), "=r"(d[22]), "=r"(d[23]),
                  "=r"(d[24]), "=r"(d[25]), "=r"(d[26]), "=r"(d[27]),
                  "=r"(d[28]), "=r"(d[29]), "=r"(d[30]), "=r"(d[31])
                : "r"(tmem + ((tp & 1) ? TM_D1 : TM_D0)));
            asm volatile("tcgen05.wait::ld.sync.aligned;" ::: "memory");
            asm volatile("tcgen05.fence::before_thread_sync;" ::: "memory");

#pragma unroll
            for (int q = 0; q < 8; ++q) {
                float4 bq = b2s[q];
                float4 o4;
                o4.x = swish_fast(__uint_as_float(d[4 * q + 0]) + bq.x);
                o4.y = swish_fast(__uint_as_float(d[4 * q + 1]) + bq.y);
                o4.z = swish_fast(__uint_as_float(d[4 * q + 2]) + bq.z);
                o4.w = swish_fast(__uint_as_float(d[4 * q + 3]) + bq.w);
                *(float4*)(out + orow_prev + 4 * q) = o4;
            }
        }
        orow_prev = ((size_t)i * N_NODES + j) * OUT;
    }

    // ---- tail epilogue (tile JITERS-1) ----
    {
        const int tp = JITERS - 1;
        mbar_wait(sb + SM_MBAR0 + (unsigned)(tp & 1) * 8, (tp >> 1) & 1);
        asm volatile("tcgen05.fence::after_thread_sync;" ::: "memory");

        unsigned d[32];
        asm volatile(
            "tcgen05.ld.sync.aligned.32x32b.x32.b32 "
            "{%0, %1, %2, %3, %4, %5, %6, %7, "
            " %8, %9, %10, %11, %12, %13, %14, %15, "
            " %16, %17, %18, %19, %20, %21, %22, %23, "
            " %24, %25, %26, %27, %28, %29, %30, %31}, [%32];"
            : "=r"(d[0]),  "=r"(d[1]),  "=r"(d[2]),  "=r"(d[3]),
              "=r"(d[4]),  "=r"(d[5]),  "=r"(d[6]),  "=r"(d[7]),
              "=r"(d[8]),  "=r"(d[9]),  "=r"(d[10]), "=r"(d[11]),
              "=r"(d[12]), "=r"(d[13]), "=r"(d[14]), "=r"(d[15]),
              "=r"(d[16]), "=r"(d[17]), "=r"(d[18]), "=r"(d[19]),
              "=r"(d[20]), "=r"(d[21]), "=r"(d[22]), "=r"(d[23]),
              "=r"(d[24]), "=r"(d[25]), "=r"(d[26]), "=r"(d[27]),
              "=r"(d[28]), "=r"(d[29]), "=r"(d[30]), "=r"(d[31])
            : "r"(tmem + ((tp & 1) ? TM_D1 : TM_D0)));
        asm volatile("tcgen05.wait::ld.sync.aligned;" ::: "memory");
        asm volatile("tcgen05.fence::before_thread_sync;" ::: "memory");

#pragma unroll
        for (int q = 0; q < 8; ++q) {
            float4 bq = b2s[q];
            float4 o4;
            o4.x = swish_fast(__uint_as_float(d[4 * q + 0]) + bq.x);
            o4.y = swish_fast(__uint_as_float(d[4 * q + 1]) + bq.y);
            o4.z = swish_fast(__uint_as_float(d[4 * q + 2]) + bq.z);
            o4.w = swish_fast(__uint_as_float(d[4 * q + 3]) + bq.w);
            *(float4*)(out + orow_prev + 4 * q) = o4;
        }
    }

    __syncthreads();
    if (tid == 0) {
        mbar_inval(sb + SM_MBAR0);
        mbar_inval(sb + SM_MBAR1);
    }
    __syncthreads();
    if (warp == 0) {
        asm volatile("tcgen05.dealloc.cta_group::1.sync.aligned.b32 %0, %1;"
                     :: "r"(tmem), "r"(128u));
    }
#else
    // ===================== scalar FFMA2 fallback =====================
    const float4* Ar  = (const float4*)(g_A + i * HID);
    float2* W2p = (float2*)(smem + FB_W2P);
    float*  b1f = (float*)(smem + FB_B1);
    float*  b2f = (float*)(smem + FB_B2);
    for (int p = tid; p < HID * 16; p += 128) {
        int h = p >> 4, o2 = p & 15;
        W2p[h * 16 + o2] = make_float2(W2[(2 * o2) * HID + h],
                                       W2[(2 * o2 + 1) * HID + h]);
    }
    if (tid < HID) b1f[tid] = b1[tid];
    if (tid < OUT) b2f[tid] = b2[tid];
    __syncthreads();

    const unsigned w2sm = smem_u32(W2p);

    for (int it = 0; it < JITERS; ++it) {
        const int j = jblk + it * J_TILE + jl;
        float dx = cx - Coords[j * 3 + 0];
        float dy = cy - Coords[j * 3 + 1];
        float dz = cz - Coords[j * 3 + 2];
        float d2 = dx * dx + dy * dy + dz * dz;
        float dist = (d2 > 0.f) ? d2 * rsqrtf(d2) : 0.f;
        const float w = Edges[(size_t)i * N_NODES + j] * dist;

        const float4* Br = (const float4*)(g_B + j * HID);
        unsigned long long acc[16];
#pragma unroll
        for (int o2 = 0; o2 < 16; ++o2) acc[o2] = 0ull;

#pragma unroll 4
        for (int c = 0; c < 16; ++c) {
            float4 a  = __ldg(Ar + c);
            float4 bb = __ldg(Br + c);
            float4 bv = __ldg(((const float4*)b1) + c);
            float av[4] = {a.x, a.y, a.z, a.w};
            float pv[4] = {bb.x, bb.y, bb.z, bb.w};
            float cv[4] = {bv.x, bv.y, bv.z, bv.w};
#pragma unroll
            for (int k = 0; k < 4; ++k) {
                float g = swish_fast(fmaf(w, av[k] + pv[k], cv[k]));
                unsigned long long g2 = pack2(g, g);
                unsigned base = w2sm + (unsigned)(4 * c + k) * (16 * 8);
#pragma unroll
                for (int o2 = 0; o2 < 16; ++o2) {
                    unsigned long long wv = lds_u64(base + o2 * 8);
                    FFMA2(acc[o2], g2, wv);
                }
            }
        }

        const size_t orow = ((size_t)i * N_NODES + j) * OUT;
#pragma unroll
        for (int o4 = 0; o4 < 8; ++o4) {
            float a, b, c, d;
            unpack2(acc[2 * o4 + 0], a, b);
            unpack2(acc[2 * o4 + 1], c, d);
            float4 v;
            v.x = swish_fast(a + b2f[4 * o4 + 0]);
            v.y = swish_fast(b + b2f[4 * o4 + 1]);
            v.z = swish_fast(c + b2f[4 * o4 + 2]);
            v.w = swish_fast(d + b2f[4 * o4 + 3]);
            *(float4*)(out + orow + 4 * o4) = v;
        }
    }
#endif
}

// ---------------------------------------------------------------------------
// Harness entry. Inputs: Edges, Coordinates, Embeddings, W1, b1, W2, b2.
// Output: float32 (N, N, OUT).
// ---------------------------------------------------------------------------
extern "C" void kernel_launch(void* const* d_in, const int* in_sizes, int n_in,
                              void* d_out, int out_size) {
    const float* Edges  = (const float*)d_in[0];
    const float* Coords = (const float*)d_in[1];
    const float* Emb    = (const float*)d_in[2];
    const float* W1     = (const float*)d_in[3];
    const float* b1     = (const float*)d_in[4];
    const float* W2     = (const float*)d_in[5];
    const float* b2     = (const float*)d_in[6];
    float* out = (float*)d_out;

    precompute_AB<<<(N_NODES * HID) / 256, 256>>>(Emb, W1);

    dim3 grid(N_NODES / (J_TILE * JITERS), N_NODES / I_TILE);  // (8, 128)
    edge_mlp_tc<<<grid, 128, SM_TOTAL>>>(Edges, Coords, b1, W2, b2, out);
}

// round 8
// speedup vs baseline: 1.0636x; 1.0636x over previous
#include <cuda_runtime.h>
#include <cuda_bf16.h>
#include <cuda_fp16.h>
#include <cstdint>
#include <cstddef>

#define N_NODES 1024
#define F_IN    32
#define HID     64
#define OUT     32
#define I_TILE  8
#define J_TILE  16
#define JITERS  8     // j-tiles per block

#if defined(__CUDA_ARCH__) && (defined(__CUDA_ARCH_FEAT_SM103_ALL) || \
                               defined(__CUDA_ARCH_FEAT_SM100_ALL) || \
                               defined(__CUDA_ARCH_FAMILY_SPECIFIC__))
#define USE_TC 1
#else
#define USE_TC 0
#endif

__device__ float g_A[N_NODES * HID];   // A[i,h] = Emb[i,:] . W1[h, :F]
__device__ float g_B[N_NODES * HID];   // B[j,h] = Emb[j,:] . W1[h, F:]

// ---------------------------------------------------------------------------
// Kernel 1: A/B precompute (tiny)
// ---------------------------------------------------------------------------
__global__ void precompute_AB(const float* __restrict__ Emb,
                              const float* __restrict__ W1) {
    int idx = blockIdx.x * blockDim.x + threadIdx.x;
    int i = idx >> 6;
    int h = idx & 63;
    const float* er = Emb + i * F_IN;
    const float* wr = W1 + h * (2 * F_IN);
    float sa = 0.f, sb = 0.f;
#pragma unroll
    for (int f = 0; f < F_IN; ++f) {
        float e = er[f];
        sa = fmaf(e, wr[f], sa);
        sb = fmaf(e, wr[F_IN + f], sb);
    }
    g_A[idx] = sa;
    g_B[idx] = sb;
}

// ---------------------------------------------------------------------------
// Helpers
// ---------------------------------------------------------------------------
__device__ __forceinline__ unsigned smem_u32(const void* p) {
    unsigned a;
    asm("{ .reg .u64 t; cvta.to.shared.u64 t, %1; cvt.u32.u64 %0, t; }"
        : "=r"(a) : "l"(p));
    return a;
}

__device__ __forceinline__ unsigned long long pack2(float lo, float hi) {
    unsigned long long r;
    asm("mov.b64 %0, {%1, %2};"
        : "=l"(r) : "r"(__float_as_uint(lo)), "r"(__float_as_uint(hi)));
    return r;
}

__device__ __forceinline__ void unpack2(unsigned long long v, float& lo, float& hi) {
    unsigned a, b;
    asm("mov.b64 {%0, %1}, %2;" : "=r"(a), "=r"(b) : "l"(v));
    lo = __uint_as_float(a);
    hi = __uint_as_float(b);
}

__device__ __forceinline__ unsigned long long lds_u64(unsigned addr) {
    unsigned long long r;
    asm volatile("ld.shared.b64 %0, [%1];" : "=l"(r) : "r"(addr));
    return r;
}

#define FFMA2(acc, a, b) \
    asm("fma.rn.f32x2 %0, %1, %2, %0;" : "+l"(acc) : "l"(a), "l"(b))

// swish(x) = x*sigmoid(x) = h*(1+tanh(h)), h = x/2.  1 MUFU instead of 2.
__device__ __forceinline__ float swish_fast(float x) {
    float h = 0.5f * x;
    float t;
    asm("tanh.approx.f32 %0, %1;" : "=f"(t) : "f"(h));
    return fmaf(h, t, h);
}

// pack two f32 -> f16x2 (first arg -> low half)
__device__ __forceinline__ unsigned cvt2f16(float lo, float hi) {
    unsigned r;
    asm("cvt.rn.f16x2.f32 %0, %1, %2;" : "=r"(r) : "f"(hi), "f"(lo));
    return r;
}

#if USE_TC
__device__ __forceinline__ bool elect_one() {
    unsigned pred;
    asm volatile("{\n\t.reg .pred p;\n\telect.sync _|p, 0xFFFFFFFF;\n\t"
                 "selp.b32 %0, 1, 0, p;\n\t}" : "=r"(pred));
    return pred != 0;
}

__device__ __forceinline__ void mbar_init(unsigned addr, unsigned cnt) {
    asm volatile("mbarrier.init.shared.b64 [%0], %1;" :: "r"(addr), "r"(cnt) : "memory");
}

__device__ __forceinline__ void mbar_inval(unsigned addr) {
    asm volatile("mbarrier.inval.shared.b64 [%0];" :: "r"(addr) : "memory");
}

__device__ __forceinline__ void mbar_wait(unsigned addr, unsigned parity) {
    asm volatile(
        "{\n\t.reg .pred P;\n\t"
        "WL_%=:\n\t"
        "mbarrier.try_wait.parity.acquire.cta.shared::cta.b64 P, [%0], %1, 0x989680;\n\t"
        "@P bra.uni WD_%=;\n\t"
        "bra.uni WL_%=;\n\t"
        "WD_%=:\n\t}"
        :: "r"(addr), "r"(parity) : "memory");
}

// SW128 K-major smem descriptor: layout=2, version=1, SBO=64, LBO=1
__device__ __forceinline__ unsigned long long sdesc(unsigned addr) {
    const unsigned long long base =
        (2ull << 61) | (1ull << 46) | (64ull << 32) | (1ull << 16);
    return base | ((unsigned long long)(addr >> 4) & 0x3FFF);
}

// idesc kind::f16: dtype=F32, atype=btype=F16(0), N=32, M=128 -> 0x8080010
#define MMA_IDESC ((1u << 4) | ((OUT / 8) << 17) | (8u << 24))

// TS-form: A operand in TMEM
__device__ __forceinline__ void mma_f16_ts(unsigned d_tmem, unsigned a_tmem,
                                           unsigned long long b_desc,
                                           unsigned en) {
    asm volatile(
        "{\n\t.reg .pred p;\n\t"
        "setp.ne.u32 p, %5, 0;\n\t"
        "tcgen05.mma.cta_group::1.kind::f16 [%0], [%1], %2, %3, {%4, %4, %4, %4}, p;\n\t"
        "}"
        :: "r"(d_tmem), "r"(a_tmem), "l"(b_desc), "r"(MMA_IDESC), "r"(0u), "r"(en)
        : "memory");
}
#endif  // USE_TC

// ---------------------------------------------------------------------------
// Dynamic SMEM layout. Total 15744 B.
// ---------------------------------------------------------------------------
#define SM_TMEM  0
#define SM_MBAR0 8
#define SM_MBAR1 16
#define SM_WHI   1024                     // 32 x 64 f16 SW128 = 4KB
#define SM_WLO   (SM_WHI + 4096)          // 5120
#define SM_BS    (SM_WLO + 4096)          // 9216 (16 rows x 64 f, XOR layout)
#define SM_AS    (SM_BS + 4096)           // 13312 (8 rows x 64 f = 2KB)
#define SM_B1    (SM_AS + 2048)           // 15360
#define SM_B2    (SM_B1 + 256)            // 15616
#define SM_TOTAL (SM_B2 + 128)            // 15744

// Fallback layout (front of same buffer)
#define FB_W2P  0
#define FB_B1   (FB_W2P + HID * 16 * 8)
#define FB_B2   (FB_B1 + HID * 4)

#define SWZ(off) ((off) ^ (((off) >> 3) & 0x70))
// Bs addressing: row jl (256B), float4 slot c4 stored at (c4 ^ jl)*16
#define BS_ADDR(jl, c4) (SM_BS + ((jl) << 8) + ((unsigned)((c4) ^ (jl)) << 4))

// TMEM column offsets (alloc 128 cols)
#define TM_D0 0
#define TM_D1 32
#define TM_A0 64
#define TM_A1 96

// ---------------------------------------------------------------------------
// Kernel 2: fused edge MLP; h1 goes regs -> TMEM (tcgen05.st) -> TS-mode MMA.
// Block = 128 thr; per iter: tile 8 i x 16 j (M=128), N=32, K=64.
// ---------------------------------------------------------------------------
__global__ __launch_bounds__(128)
void edge_mlp_tc(const float* __restrict__ Edges,
                 const float* __restrict__ Coords,
                 const float* __restrict__ b1,
                 const float* __restrict__ W2,
                 const float* __restrict__ b2,
                 float* __restrict__ out) {
    extern __shared__ char smem[];
    const int tid  = threadIdx.x;
    const int warp = tid >> 5;
    const int ibase = blockIdx.y * I_TILE;
    const int jblk  = blockIdx.x * (J_TILE * JITERS);

    const int i  = ibase + (tid >> 4);
    const int jl = tid & 15;

    const float cx = Coords[i * 3 + 0];
    const float cy = Coords[i * 3 + 1];
    const float cz = Coords[i * 3 + 2];

#if USE_TC
    const unsigned sb = smem_u32(smem);
    if (warp == 0) {
        asm volatile("tcgen05.alloc.cta_group::1.sync.aligned.shared::cta.b32 [%0], %1;"
                     :: "r"(sb + SM_TMEM), "r"(128u) : "memory");
        asm volatile("tcgen05.relinquish_alloc_permit.cta_group::1.sync.aligned;");
    }
    if (tid == 0) {
        mbar_init(sb + SM_MBAR0, 1);
        mbar_init(sb + SM_MBAR1, 1);
    }

    // ---- stage W2 (fp16 hi/lo, SW128), A i-rows, b1, b2 — once per block ----
    for (int p = tid; p < OUT * 32; p += 128) {
        int o = p >> 5, h2 = p & 31;
        float w0 = W2[o * HID + 2 * h2];
        float w1 = W2[o * HID + 2 * h2 + 1];
        unsigned hi = cvt2f16(w0, w1);
        float r0 = w0 - __half2float(__ushort_as_half((unsigned short)(hi & 0xFFFF)));
        float r1 = w1 - __half2float(__ushort_as_half((unsigned short)(hi >> 16)));
        unsigned lo = cvt2f16(r0, r1);
        unsigned sw = SWZ((unsigned)(o * 128 + h2 * 4));
        *(unsigned*)(smem + SM_WHI + sw) = hi;
        *(unsigned*)(smem + SM_WLO + sw) = lo;
    }
    {
        const float4* src = (const float4*)(g_A + ibase * HID);
        for (int p = tid; p < 128; p += 128)
            ((float4*)(smem + SM_AS))[p] = src[p];
        if (tid < 16) ((float4*)(smem + SM_B1))[tid] = ((const float4*)b1)[tid];
        else if (tid < 24) ((float4*)(smem + SM_B2))[tid - 16] = ((const float4*)b2)[tid - 16];
    }
    asm volatile("fence.proxy.async.shared::cta;" ::: "memory");
    __syncthreads();

    unsigned tmem;
    asm("ld.shared.b32 %0, [%1];" : "=r"(tmem) : "r"(sb + SM_TMEM));

    const unsigned long long whiD = sdesc(sb + SM_WHI);
    const unsigned long long wloD = sdesc(sb + SM_WLO);
    const unsigned warp_off = (unsigned)warp << 21;

    const float4* Asr = (const float4*)(smem + SM_AS + (tid >> 4) * 256);
    const float4* b1s = (const float4*)(smem + SM_B1);
    const float4* b2s = (const float4*)(smem + SM_B2);

    size_t orow_prev = 0;

    for (int t = 0; t < JITERS; ++t) {
        const int jbase = jblk + t * J_TILE;

        // ---- stage B j-tile (coalesced, XOR layout) ----
        {
            const float4* src = (const float4*)(g_B + jbase * HID);
#pragma unroll
            for (int p = tid; p < 256; p += 128) {
                int jj = p >> 4, c4 = p & 15;
                *(float4*)(smem + BS_ADDR(jj, c4)) = src[p];
            }
        }
        __syncthreads();

        const int j = jbase + jl;
        float dx = cx - Coords[j * 3 + 0];
        float dy = cy - Coords[j * 3 + 1];
        float dz = cz - Coords[j * 3 + 2];
        float d2 = dx * dx + dy * dy + dz * dz;
        float dist = (d2 > 0.f) ? d2 * rsqrtf(d2) : 0.f;
        const float w = Edges[(size_t)i * N_NODES + j] * dist;

        // ---- h1 = swish(w*(A+B)+b1) -> 32 f16x2 regs ----
        unsigned v[32];
#pragma unroll
        for (int c = 0; c < 8; ++c) {
            float4 a0 = Asr[2 * c];
            float4 a1 = Asr[2 * c + 1];
            float4 p0 = *(const float4*)(smem + BS_ADDR(jl, 2 * c));
            float4 p1 = *(const float4*)(smem + BS_ADDR(jl, 2 * c + 1));
            float4 q0 = b1s[2 * c];
            float4 q1 = b1s[2 * c + 1];

            float g0 = swish_fast(fmaf(w, a0.x + p0.x, q0.x));
            float g1 = swish_fast(fmaf(w, a0.y + p0.y, q0.y));
            float g2 = swish_fast(fmaf(w, a0.z + p0.z, q0.z));
            float g3 = swish_fast(fmaf(w, a0.w + p0.w, q0.w));
            float g4 = swish_fast(fmaf(w, a1.x + p1.x, q1.x));
            float g5 = swish_fast(fmaf(w, a1.y + p1.y, q1.y));
            float g6 = swish_fast(fmaf(w, a1.z + p1.z, q1.z));
            float g7 = swish_fast(fmaf(w, a1.w + p1.w, q1.w));

            v[4 * c + 0] = cvt2f16(g0, g1);
            v[4 * c + 1] = cvt2f16(g2, g3);
            v[4 * c + 2] = cvt2f16(g4, g5);
            v[4 * c + 3] = cvt2f16(g6, g7);
        }

        // ---- store h1 to TMEM A buffer (warp-collective) ----
        const unsigned atm = tmem + ((t & 1) ? TM_A1 : TM_A0);
        asm volatile(
            "tcgen05.st.sync.aligned.32x32b.x32.b32 [%0], "
            "{%1, %2, %3, %4, %5, %6, %7, %8, "
            " %9, %10, %11, %12, %13, %14, %15, %16, "
            " %17, %18, %19, %20, %21, %22, %23, %24, "
            " %25, %26, %27, %28, %29, %30, %31, %32};"
            :: "r"(atm + warp_off),
               "r"(v[0]),  "r"(v[1]),  "r"(v[2]),  "r"(v[3]),
               "r"(v[4]),  "r"(v[5]),  "r"(v[6]),  "r"(v[7]),
               "r"(v[8]),  "r"(v[9]),  "r"(v[10]), "r"(v[11]),
               "r"(v[12]), "r"(v[13]), "r"(v[14]), "r"(v[15]),
               "r"(v[16]), "r"(v[17]), "r"(v[18]), "r"(v[19]),
               "r"(v[20]), "r"(v[21]), "r"(v[22]), "r"(v[23]),
               "r"(v[24]), "r"(v[25]), "r"(v[26]), "r"(v[27]),
               "r"(v[28]), "r"(v[29]), "r"(v[30]), "r"(v[31])
            : "memory");
        asm volatile("tcgen05.wait::st.sync.aligned;" ::: "memory");
        asm volatile("tcgen05.fence::before_thread_sync;" ::: "memory");
        __syncthreads();

        // ---- issue MMA[t] (TS form): D[t%2] = A_tmem * (Whi + Wlo) ----
        if (warp == 0 && elect_one()) {
            asm volatile("tcgen05.fence::after_thread_sync;" ::: "memory");
            const unsigned dtm = tmem + ((t & 1) ? TM_D1 : TM_D0);
            unsigned en = 0;
#pragma unroll
            for (int k = 0; k < 4; ++k) { mma_f16_ts(dtm, atm + k * 8, whiD + 2 * k, en); en = 1; }
#pragma unroll
            for (int k = 0; k < 4; ++k) { mma_f16_ts(dtm, atm + k * 8, wloD + 2 * k, 1); }
            asm volatile(
                "tcgen05.commit.cta_group::1.mbarrier::arrive::one.shared::cluster.b64 [%0];"
                :: "r"(sb + SM_MBAR0 + (unsigned)(t & 1) * 8) : "memory");
        }

        // ---- epilogue of tile t-1 (overlaps MMA[t]) ----
        if (t > 0) {
            const int tp = t - 1;
            mbar_wait(sb + SM_MBAR0 + (unsigned)(tp & 1) * 8, (tp >> 1) & 1);
            asm volatile("tcgen05.fence::after_thread_sync;" ::: "memory");

            unsigned d[32];
            asm volatile(
                "tcgen05.ld.sync.aligned.32x32b.x32.b32 "
                "{%0, %1, %2, %3, %4, %5, %6, %7, "
                " %8, %9, %10, %11, %12, %13, %14, %15, "
                " %16, %17, %18, %19, %20, %21, %22, %23, "
                " %24, %25, %26, %27, %28, %29, %30, %31}, [%32];"
                : "=r"(d[0]),  "=r"(d[1]),  "=r"(d[2]),  "=r"(d[3]),
                  "=r"(d[4]),  "=r"(d[5]),  "=r"(d[6]),  "=r"(d[7]),
                  "=r"(d[8]),  "=r"(d[9]),  "=r"(d[10]), "=r"(d[11]),
                  "=r"(d[12]), "=r"(d[13]), "=r"(d[14]), "=r"(d[15]),
                  "=r"(d[16]), "=r"(d[17]), "=r"(d[18]), "=r"(d[19]),
                  "=r"(d[20]), "=r"(d[21]), "=r"(d[22]), "=r"(d[23]),
                  "=r"(d[24]), "=r"(d[25]), "=r"(d[26]), "=r"(d[27]),
                  "=r"(d[28]), "=r"(d[29]), "=r"(d[30]), "=r"(d[31])
                : "r"(tmem + ((tp & 1) ? TM_D1 : TM_D0)));
            asm volatile("tcgen05.wait::ld.sync.aligned;" ::: "memory");
            asm volatile("tcgen05.fence::before_thread_sync;" ::: "memory");

#pragma unroll
            for (int q = 0; q < 8; ++q) {
                float4 bq = b2s[q];
                float4 o4;
                o4.x = swish_fast(__uint_as_float(d[4 * q + 0]) + bq.x);
                o4.y = swish_fast(__uint_as_float(d[4 * q + 1]) + bq.y);
                o4.z = swish_fast(__uint_as_float(d[4 * q + 2]) + bq.z);
                o4.w = swish_fast(__uint_as_float(d[4 * q + 3]) + bq.w);
                *(float4*)(out + orow_prev + 4 * q) = o4;
            }
        }
        orow_prev = ((size_t)i * N_NODES + j) * OUT;
    }

    // ---- tail epilogue (tile JITERS-1) ----
    {
        const int tp = JITERS - 1;
        mbar_wait(sb + SM_MBAR0 + (unsigned)(tp & 1) * 8, (tp >> 1) & 1);
        asm volatile("tcgen05.fence::after_thread_sync;" ::: "memory");

        unsigned d[32];
        asm volatile(
            "tcgen05.ld.sync.aligned.32x32b.x32.b32 "
            "{%0, %1, %2, %3, %4, %5, %6, %7, "
            " %8, %9, %10, %11, %12, %13, %14, %15, "
            " %16, %17, %18, %19, %20, %21, %22, %23, "
            " %24, %25, %26, %27, %28, %29, %30, %31}, [%32];"
            : "=r"(d[0]),  "=r"(d[1]),  "=r"(d[2]),  "=r"(d[3]),
              "=r"(d[4]),  "=r"(d[5]),  "=r"(d[6]),  "=r"(d[7]),
              "=r"(d[8]),  "=r"(d[9]),  "=r"(d[10]), "=r"(d[11]),
              "=r"(d[12]), "=r"(d[13]), "=r"(d[14]), "=r"(d[15]),
              "=r"(d[16]), "=r"(d[17]), "=r"(d[18]), "=r"(d[19]),
              "=r"(d[20]), "=r"(d[21]), "=r"(d[22]), "=r"(d[23]),
              "=r"(d[24]), "=r"(d[25]), "=r"(d[26]), "=r"(d[27]),
              "=r"(d[28]), "=r"(d[29]), "=r"(d[30]), "=r"(d[31])
            : "r"(tmem + ((tp & 1) ? TM_D1 : TM_D0)));
        asm volatile("tcgen05.wait::ld.sync.aligned;" ::: "memory");
        asm volatile("tcgen05.fence::before_thread_sync;" ::: "memory");

#pragma unroll
        for (int q = 0; q < 8; ++q) {
            float4 bq = b2s[q];
            float4 o4;
            o4.x = swish_fast(__uint_as_float(d[4 * q + 0]) + bq.x);
            o4.y = swish_fast(__uint_as_float(d[4 * q + 1]) + bq.y);
            o4.z = swish_fast(__uint_as_float(d[4 * q + 2]) + bq.z);
            o4.w = swish_fast(__uint_as_float(d[4 * q + 3]) + bq.w);
            *(float4*)(out + orow_prev + 4 * q) = o4;
        }
    }

    __syncthreads();
    if (tid == 0) {
        mbar_inval(sb + SM_MBAR0);
        mbar_inval(sb + SM_MBAR1);
    }
    __syncthreads();
    if (warp == 0) {
        asm volatile("tcgen05.dealloc.cta_group::1.sync.aligned.b32 %0, %1;"
                     :: "r"(tmem), "r"(128u));
    }
#else
    // ===================== scalar FFMA2 fallback =====================
    const float4* Ar  = (const float4*)(g_A + i * HID);
    float2* W2p = (float2*)(smem + FB_W2P);
    float*  b1f = (float*)(smem + FB_B1);
    float*  b2f = (float*)(smem + FB_B2);
    for (int p = tid; p < HID * 16; p += 128) {
        int h = p >> 4, o2 = p & 15;
        W2p[h * 16 + o2] = make_float2(W2[(2 * o2) * HID + h],
                                       W2[(2 * o2 + 1) * HID + h]);
    }
    if (tid < HID) b1f[tid] = b1[tid];
    if (tid < OUT) b2f[tid] = b2[tid];
    __syncthreads();

    const unsigned w2sm = smem_u32(W2p);

    for (int it = 0; it < JITERS; ++it) {
        const int j = jblk + it * J_TILE + jl;
        float dx = cx - Coords[j * 3 + 0];
        float dy = cy - Coords[j * 3 + 1];
        float dz = cz - Coords[j * 3 + 2];
        float d2 = dx * dx + dy * dy + dz * dz;
        float dist = (d2 > 0.f) ? d2 * rsqrtf(d2) : 0.f;
        const float w = Edges[(size_t)i * N_NODES + j] * dist;

        const float4* Br = (const float4*)(g_B + j * HID);
        unsigned long long acc[16];
#pragma unroll
        for (int o2 = 0; o2 < 16; ++o2) acc[o2] = 0ull;

#pragma unroll 4
        for (int c = 0; c < 16; ++c) {
            float4 a  = __ldg(Ar + c);
            float4 bb = __ldg(Br + c);
            float4 bv = __ldg(((const float4*)b1) + c);
            float av[4] = {a.x, a.y, a.z, a.w};
            float pv[4] = {bb.x, bb.y, bb.z, bb.w};
            float cv[4] = {bv.x, bv.y, bv.z, bv.w};
#pragma unroll
            for (int k = 0; k < 4; ++k) {
                float g = swish_fast(fmaf(w, av[k] + pv[k], cv[k]));
                unsigned long long g2 = pack2(g, g);
                unsigned base = w2sm + (unsigned)(4 * c + k) * (16 * 8);
#pragma unroll
                for (int o2 = 0; o2 < 16; ++o2) {
                    unsigned long long wv = lds_u64(base + o2 * 8);
                    FFMA2(acc[o2], g2, wv);
                }
            }
        }

        const size_t orow = ((size_t)i * N_NODES + j) * OUT;
#pragma unroll
        for (int o4 = 0; o4 < 8; ++o4) {
            float a, b, c, d;
            unpack2(acc[2 * o4 + 0], a, b);
            unpack2(acc[2 * o4 + 1], c, d);
            float4 v;
            v.x = swish_fast(a + b2f[4 * o4 + 0]);
            v.y = swish_fast(b + b2f[4 * o4 + 1]);
            v.z = swish_fast(c + b2f[4 * o4 + 2]);
            v.w = swish_fast(d + b2f[4 * o4 + 3]);
            *(float4*)(out + orow + 4 * o4) = v;
        }
    }
#endif
}

// ---------------------------------------------------------------------------
// Harness entry. Inputs: Edges, Coordinates, Embeddings, W1, b1, W2, b2.
// Output: float32 (N, N, OUT).
// ---------------------------------------------------------------------------
extern "C" void kernel_launch(void* const* d_in, const int* in_sizes, int n_in,
                              void* d_out, int out_size) {
    const float* Edges  = (const float*)d_in[0];
    const float* Coords = (const float*)d_in[1];
    const float* Emb    = (const float*)d_in[2];
    const float* W1     = (const float*)d_in[3];
    const float* b1     = (const float*)d_in[4];
    const float* W2     = (const float*)d_in[5];
    const float* b2     = (const float*)d_in[6];
    float* out = (float*)d_out;

    precompute_AB<<<(N_NODES * HID) / 256, 256>>>(Emb, W1);

    dim3 grid(N_NODES / (J_TILE * JITERS), N_NODES / I_TILE);  // (8, 128)
    edge_mlp_tc<<<grid, 128, SM_TOTAL>>>(Edges, Coords, b1, W2, b2, out);
}

// round 9
// speedup vs baseline: 1.1337x; 1.0660x over previous
#include <cuda_runtime.h>
#include <cuda_bf16.h>
#include <cuda_fp16.h>
#include <cstdint>
#include <cstddef>

#define N_NODES 1024
#define F_IN    32
#define HID     64
#define OUT     32
#define I_TILE  8
#define J_TILE  16
#define JITERS  8     // j-tiles per block
#define THREADS 256

#if defined(__CUDA_ARCH__) && (defined(__CUDA_ARCH_FEAT_SM103_ALL) || \
                               defined(__CUDA_ARCH_FEAT_SM100_ALL) || \
                               defined(__CUDA_ARCH_FAMILY_SPECIFIC__))
#define USE_TC 1
#else
#define USE_TC 0
#endif

__device__ float g_A[N_NODES * HID];   // A[i,h] = Emb[i,:] . W1[h, :F]
__device__ float g_B[N_NODES * HID];   // B[j,h] = Emb[j,:] . W1[h, F:]

// ---------------------------------------------------------------------------
// Kernel 1: A/B precompute (tiny)
// ---------------------------------------------------------------------------
__global__ void precompute_AB(const float* __restrict__ Emb,
                              const float* __restrict__ W1) {
    int idx = blockIdx.x * blockDim.x + threadIdx.x;
    int i = idx >> 6;
    int h = idx & 63;
    const float* er = Emb + i * F_IN;
    const float* wr = W1 + h * (2 * F_IN);
    float sa = 0.f, sb = 0.f;
#pragma unroll
    for (int f = 0; f < F_IN; ++f) {
        float e = er[f];
        sa = fmaf(e, wr[f], sa);
        sb = fmaf(e, wr[F_IN + f], sb);
    }
    g_A[idx] = sa;
    g_B[idx] = sb;
}

// ---------------------------------------------------------------------------
// Helpers
// ---------------------------------------------------------------------------
__device__ __forceinline__ unsigned smem_u32(const void* p) {
    unsigned a;
    asm("{ .reg .u64 t; cvta.to.shared.u64 t, %1; cvt.u32.u64 %0, t; }"
        : "=r"(a) : "l"(p));
    return a;
}

__device__ __forceinline__ unsigned long long pack2(float lo, float hi) {
    unsigned long long r;
    asm("mov.b64 %0, {%1, %2};"
        : "=l"(r) : "r"(__float_as_uint(lo)), "r"(__float_as_uint(hi)));
    return r;
}

__device__ __forceinline__ void unpack2(unsigned long long v, float& lo, float& hi) {
    unsigned a, b;
    asm("mov.b64 {%0, %1}, %2;" : "=r"(a), "=r"(b) : "l"(v));
    lo = __uint_as_float(a);
    hi = __uint_as_float(b);
}

__device__ __forceinline__ unsigned long long lds_u64(unsigned addr) {
    unsigned long long r;
    asm volatile("ld.shared.b64 %0, [%1];" : "=l"(r) : "r"(addr));
    return r;
}

#define FFMA2(acc, a, b) \
    asm("fma.rn.f32x2 %0, %1, %2, %0;" : "+l"(acc) : "l"(a), "l"(b))

// swish(x) = x*sigmoid(x) = h*(1+tanh(h)), h = x/2.  1 MUFU.
__device__ __forceinline__ float swish_fast(float x) {
    float h = 0.5f * x;
    float t;
    asm("tanh.approx.f32 %0, %1;" : "=f"(t) : "f"(h));
    return fmaf(h, t, h);
}

// pack two f32 -> f16x2 (first arg -> low half)
__device__ __forceinline__ unsigned cvt2f16(float lo, float hi) {
    unsigned r;
    asm("cvt.rn.f16x2.f32 %0, %1, %2;" : "=r"(r) : "f"(hi), "f"(lo));
    return r;
}

#if USE_TC
__device__ __forceinline__ bool elect_one() {
    unsigned pred;
    asm volatile("{\n\t.reg .pred p;\n\telect.sync _|p, 0xFFFFFFFF;\n\t"
                 "selp.b32 %0, 1, 0, p;\n\t}" : "=r"(pred));
    return pred != 0;
}

__device__ __forceinline__ void mbar_init(unsigned addr, unsigned cnt) {
    asm volatile("mbarrier.init.shared.b64 [%0], %1;" :: "r"(addr), "r"(cnt) : "memory");
}

__device__ __forceinline__ void mbar_inval(unsigned addr) {
    asm volatile("mbarrier.inval.shared.b64 [%0];" :: "r"(addr) : "memory");
}

__device__ __forceinline__ void mbar_arrive(unsigned addr) {
    asm volatile("mbarrier.arrive.shared.b64 _, [%0];" :: "r"(addr) : "memory");
}

__device__ __forceinline__ void mbar_wait(unsigned addr, unsigned parity) {
    asm volatile(
        "{\n\t.reg .pred P;\n\t"
        "WL_%=:\n\t"
        "mbarrier.try_wait.parity.acquire.cta.shared::cta.b64 P, [%0], %1, 0x989680;\n\t"
        "@P bra.uni WD_%=;\n\t"
        "bra.uni WL_%=;\n\t"
        "WD_%=:\n\t}"
        :: "r"(addr), "r"(parity) : "memory");
}

// SW128 K-major smem descriptor: layout=2, version=1, SBO=64, LBO=1
__device__ __forceinline__ unsigned long long sdesc(unsigned addr) {
    const unsigned long long base =
        (2ull << 61) | (1ull << 46) | (64ull << 32) | (1ull << 16);
    return base | ((unsigned long long)(addr >> 4) & 0x3FFF);
}

// idesc kind::f16: dtype=F32, atype=btype=F16(0), N=32, M=128 -> 0x8080010
#define MMA_IDESC ((1u << 4) | ((OUT / 8) << 17) | (8u << 24))

// TS-form: A operand in TMEM
__device__ __forceinline__ void mma_f16_ts(unsigned d_tmem, unsigned a_tmem,
                                           unsigned long long b_desc,
                                           unsigned en) {
    asm volatile(
        "{\n\t.reg .pred p;\n\t"
        "setp.ne.u32 p, %5, 0;\n\t"
        "tcgen05.mma.cta_group::1.kind::f16 [%0], [%1], %2, %3, {%4, %4, %4, %4}, p;\n\t"
        "}"
        :: "r"(d_tmem), "r"(a_tmem), "l"(b_desc), "r"(MMA_IDESC), "r"(0u), "r"(en)
        : "memory");
}
#endif  // USE_TC

// ---------------------------------------------------------------------------
// Dynamic SMEM layout. Total 21376 B.
// ---------------------------------------------------------------------------
#define SM_TMEM   0
#define SM_FULL0  8
#define SM_FULL1  16
#define SM_EMPTY0 24
#define SM_EMPTY1 32
#define SM_WHI    1024                    // 32 x 64 f16 SW128 = 4KB
#define SM_WLO    (SM_WHI + 4096)         // 5120
#define SM_BS0    (SM_WLO + 4096)         // 9216  (16 rows x 64 f, XOR layout)
#define SM_BS1    (SM_BS0 + 4096)         // 13312
#define SM_AS     (SM_BS1 + 4096)         // 17408 (8 rows x 64 f = 2KB)
#define SM_B1     (SM_AS + 2048)          // 19456
#define SM_B2     (SM_B1 + 256)           // 19712
#define SM_CJ     (SM_B2 + 128)           // 19840 (128 j x 3 f = 1536B)
#define SM_TOTAL  (SM_CJ + 1536)          // 21376

// Fallback layout (front of same buffer)
#define FB_W2P  0
#define FB_B1   (FB_W2P + HID * 16 * 8)
#define FB_B2   (FB_B1 + HID * 4)

#define SWZ(off) ((off) ^ (((off) >> 3) & 0x70))
// Bs addressing: buffer buf, row jl (256B), float4 slot c4 at (c4 ^ jl)*16
#define BS_ADDR(buf, jl, c4) \
    (SM_BS0 + ((unsigned)(buf) << 12) + ((jl) << 8) + ((unsigned)((c4) ^ (jl)) << 4))

// TMEM column offsets (alloc 128 cols)
#define TM_D0 0
#define TM_D1 32
#define TM_A0 64
#define TM_A1 96

// ---------------------------------------------------------------------------
// Kernel 2: warp-specialized fused edge MLP.
// 256 thr: warps 0-3 producers (B stage, h1, STTM, MMA, commit),
//          warps 4-7 consumers (full-wait, LDTM, swish, store).
// Per iter: tile 8 i x 16 j (M=128), N=32, K=64. 2-slot full/empty mbar ring.
// ---------------------------------------------------------------------------
__global__ __launch_bounds__(THREADS, 3)
void edge_mlp_tc(const float* __restrict__ Edges,
                 const float* __restrict__ Coords,
                 const float* __restrict__ b1,
                 const float* __restrict__ W2,
                 const float* __restrict__ b2,
                 float* __restrict__ out) {
    extern __shared__ char smem[];
    const int tid  = threadIdx.x;
    const int warp = tid >> 5;
    const int ibase = blockIdx.y * I_TILE;
    const int jblk  = blockIdx.x * (J_TILE * JITERS);

#if USE_TC
    const unsigned sb = smem_u32(smem);
    if (warp == 0) {
        asm volatile("tcgen05.alloc.cta_group::1.sync.aligned.shared::cta.b32 [%0], %1;"
                     :: "r"(sb + SM_TMEM), "r"(128u) : "memory");
        asm volatile("tcgen05.relinquish_alloc_permit.cta_group::1.sync.aligned;");
    }
    if (tid == 0) {
        mbar_init(sb + SM_FULL0, 1);
        mbar_init(sb + SM_FULL1, 1);
        mbar_init(sb + SM_EMPTY0, 4);
        mbar_init(sb + SM_EMPTY1, 4);
    }

    // ---- one-time staging: W2 (fp16 hi/lo, SW128), A rows, b1, b2, Cj ----
    for (int p = tid; p < OUT * 32; p += THREADS) {
        int o = p >> 5, h2 = p & 31;
        float w0 = W2[o * HID + 2 * h2];
        float w1 = W2[o * HID + 2 * h2 + 1];
        unsigned hi = cvt2f16(w0, w1);
        float r0 = w0 - __half2float(__ushort_as_half((unsigned short)(hi & 0xFFFF)));
        float r1 = w1 - __half2float(__ushort_as_half((unsigned short)(hi >> 16)));
        unsigned lo = cvt2f16(r0, r1);
        unsigned sw = SWZ((unsigned)(o * 128 + h2 * 4));
        *(unsigned*)(smem + SM_WHI + sw) = hi;
        *(unsigned*)(smem + SM_WLO + sw) = lo;
    }
    if (tid < 128)
        ((float4*)(smem + SM_AS))[tid] = ((const float4*)(g_A + ibase * HID))[tid];
    if (tid < 16) ((float4*)(smem + SM_B1))[tid] = ((const float4*)b1)[tid];
    else if (tid < 24) ((float4*)(smem + SM_B2))[tid - 16] = ((const float4*)b2)[tid - 16];
    for (int p = tid; p < 3 * J_TILE * JITERS; p += THREADS)
        ((float*)(smem + SM_CJ))[p] = Coords[jblk * 3 + p];

    asm volatile("fence.proxy.async.shared::cta;" ::: "memory");
    __syncthreads();

    unsigned tmem;
    asm("ld.shared.b32 %0, [%1];" : "=r"(tmem) : "r"(sb + SM_TMEM));

    if (tid < 128) {
        // =========================== PRODUCERS ===========================
        const int ptid = tid;
        const int irow = ptid >> 4;
        const int i    = ibase + irow;
        const int jl   = ptid & 15;
        const unsigned warp_off = (unsigned)warp << 21;

        const float cx = Coords[i * 3 + 0];
        const float cy = Coords[i * 3 + 1];
        const float cz = Coords[i * 3 + 2];

        const float4* Asr = (const float4*)(smem + SM_AS + irow * 256);
        const float4* b1s = (const float4*)(smem + SM_B1);
        const float*  CjS = (const float*)(smem + SM_CJ);
        const unsigned long long whiD = sdesc(sb + SM_WHI);
        const unsigned long long wloD = sdesc(sb + SM_WLO);

        const float* erow = Edges + (size_t)i * N_NODES + jblk + jl;
        float epre = __ldg(erow);                   // Edges for t=0

        for (int t = 0; t < JITERS; ++t) {
            const int slot = t & 1;

            // stage B tile into Bs[slot]
            {
                const float4* src = (const float4*)(g_B + (jblk + t * J_TILE) * HID);
#pragma unroll
                for (int p = ptid; p < 256; p += 128) {
                    int jj = p >> 4, c4 = p & 15;
                    *(float4*)(smem + BS_ADDR(slot, jj, c4)) = src[p];
                }
            }

            float ecur = epre;
            if (t < JITERS - 1) epre = __ldg(erow + (t + 1) * J_TILE);

            const int cjx = (t * J_TILE + jl) * 3;
            float dx = cx - CjS[cjx + 0];
            float dy = cy - CjS[cjx + 1];
            float dz = cz - CjS[cjx + 2];
            float d2 = dx * dx + dy * dy + dz * dz;
            float dist = (d2 > 0.f) ? d2 * rsqrtf(d2) : 0.f;
            const float w = ecur * dist;

            asm volatile("bar.sync 1, 128;" ::: "memory");   // Bs[slot] ready

            // h1 = swish(w*(A+B)+b1) -> 32 f16x2 regs
            unsigned v[32];
#pragma unroll
            for (int c = 0; c < 8; ++c) {
                float4 a0 = Asr[2 * c];
                float4 a1 = Asr[2 * c + 1];
                float4 p0 = *(const float4*)(smem + BS_ADDR(slot, jl, 2 * c));
                float4 p1 = *(const float4*)(smem + BS_ADDR(slot, jl, 2 * c + 1));
                float4 q0 = b1s[2 * c];
                float4 q1 = b1s[2 * c + 1];

                float g0 = swish_fast(fmaf(w, a0.x + p0.x, q0.x));
                float g1 = swish_fast(fmaf(w, a0.y + p0.y, q0.y));
                float g2 = swish_fast(fmaf(w, a0.z + p0.z, q0.z));
                float g3 = swish_fast(fmaf(w, a0.w + p0.w, q0.w));
                float g4 = swish_fast(fmaf(w, a1.x + p1.x, q1.x));
                float g5 = swish_fast(fmaf(w, a1.y + p1.y, q1.y));
                float g6 = swish_fast(fmaf(w, a1.z + p1.z, q1.z));
                float g7 = swish_fast(fmaf(w, a1.w + p1.w, q1.w));

                v[4 * c + 0] = cvt2f16(g0, g1);
                v[4 * c + 1] = cvt2f16(g2, g3);
                v[4 * c + 2] = cvt2f16(g4, g5);
                v[4 * c + 3] = cvt2f16(g6, g7);
            }

            // A[slot] reuse safe only after MMA[t-2] completed (full[slot] fired)
            if (t >= 2) mbar_wait(sb + SM_FULL0 + slot * 8, ((t - 2) >> 1) & 1);

            const unsigned atm = tmem + (slot ? TM_A1 : TM_A0);
            asm volatile(
                "tcgen05.st.sync.aligned.32x32b.x32.b32 [%0], "
                "{%1, %2, %3, %4, %5, %6, %7, %8, "
                " %9, %10, %11, %12, %13, %14, %15, %16, "
                " %17, %18, %19, %20, %21, %22, %23, %24, "
                " %25, %26, %27, %28, %29, %30, %31, %32};"
                :: "r"(atm + warp_off),
                   "r"(v[0]),  "r"(v[1]),  "r"(v[2]),  "r"(v[3]),
                   "r"(v[4]),  "r"(v[5]),  "r"(v[6]),  "r"(v[7]),
                   "r"(v[8]),  "r"(v[9]),  "r"(v[10]), "r"(v[11]),
                   "r"(v[12]), "r"(v[13]), "r"(v[14]), "r"(v[15]),
                   "r"(v[16]), "r"(v[17]), "r"(v[18]), "r"(v[19]),
                   "r"(v[20]), "r"(v[21]), "r"(v[22]), "r"(v[23]),
                   "r"(v[24]), "r"(v[25]), "r"(v[26]), "r"(v[27]),
                   "r"(v[28]), "r"(v[29]), "r"(v[30]), "r"(v[31])
                : "memory");
            asm volatile("tcgen05.wait::st.sync.aligned;" ::: "memory");
            asm volatile("tcgen05.fence::before_thread_sync;" ::: "memory");

            asm volatile("bar.sync 1, 128;" ::: "memory");   // all STTM done

            if (warp == 0 && elect_one()) {
                asm volatile("tcgen05.fence::after_thread_sync;" ::: "memory");
                // D[slot] reuse safe only after consumer drained it (t-2)
                if (t >= 2) mbar_wait(sb + SM_EMPTY0 + slot * 8, ((t - 2) >> 1) & 1);
                const unsigned dtm = tmem + (slot ? TM_D1 : TM_D0);
                unsigned en = 0;
#pragma unroll
                for (int k = 0; k < 4; ++k) { mma_f16_ts(dtm, atm + k * 8, whiD + 2 * k, en); en = 1; }
#pragma unroll
                for (int k = 0; k < 4; ++k) { mma_f16_ts(dtm, atm + k * 8, wloD + 2 * k, 1); }
                asm volatile(
                    "tcgen05.commit.cta_group::1.mbarrier::arrive::one.shared::cluster.b64 [%0];"
                    :: "r"(sb + SM_FULL0 + (unsigned)slot * 8) : "memory");
            }
        }
    } else {
        // =========================== CONSUMERS ===========================
        const int ctid = tid - 128;
        const int i    = ibase + (ctid >> 4);
        const int jfix = ctid & 15;
        const float4* b2s = (const float4*)(smem + SM_B2);

        for (int t = 0; t < JITERS; ++t) {
            const int slot = t & 1;
            mbar_wait(sb + SM_FULL0 + slot * 8, (t >> 1) & 1);
            asm volatile("tcgen05.fence::after_thread_sync;" ::: "memory");

            unsigned d[32];
            asm volatile(
                "tcgen05.ld.sync.aligned.32x32b.x32.b32 "
                "{%0, %1, %2, %3, %4, %5, %6, %7, "
                " %8, %9, %10, %11, %12, %13, %14, %15, "
                " %16, %17, %18, %19, %20, %21, %22, %23, "
                " %24, %25, %26, %27, %28, %29, %30, %31}, [%32];"
                : "=r"(d[0]),  "=r"(d[1]),  "=r"(d[2]),  "=r"(d[3]),
                  "=r"(d[4]),  "=r"(d[5]),  "=r"(d[6]),  "=r"(d[7]),
                  "=r"(d[8]),  "=r"(d[9]),  "=r"(d[10]), "=r"(d[11]),
                  "=r"(d[12]), "=r"(d[13]), "=r"(d[14]), "=r"(d[15]),
                  "=r"(d[16]), "=r"(d[17]), "=r"(d[18]), "=r"(d[19]),
                  "=r"(d[20]), "=r"(d[21]), "=r"(d[22]), "=r"(d[23]),
                  "=r"(d[24]), "=r"(d[25]), "=r"(d[26]), "=r"(d[27]),
                  "=r"(d[28]), "=r"(d[29]), "=r"(d[30]), "=r"(d[31])
                : "r"(tmem + (slot ? TM_D1 : TM_D0)));
            asm volatile("tcgen05.wait::ld.sync.aligned;" ::: "memory");
            asm volatile("tcgen05.fence::before_thread_sync;" ::: "memory");

            if ((tid & 31) == 0) mbar_arrive(sb + SM_EMPTY0 + slot * 8);

            const size_t orow =
                ((size_t)i * N_NODES + (jblk + t * J_TILE + jfix)) * OUT;
#pragma unroll
            for (int q = 0; q < 8; ++q) {
                float4 bq = b2s[q];
                float4 o4;
                o4.x = swish_fast(__uint_as_float(d[4 * q + 0]) + bq.x);
                o4.y = swish_fast(__uint_as_float(d[4 * q + 1]) + bq.y);
                o4.z = swish_fast(__uint_as_float(d[4 * q + 2]) + bq.z);
                o4.w = swish_fast(__uint_as_float(d[4 * q + 3]) + bq.w);
                *(float4*)(out + orow + 4 * q) = o4;
            }
        }
    }

    __syncthreads();
    if (tid == 0) {
        mbar_inval(sb + SM_FULL0);
        mbar_inval(sb + SM_FULL1);
        mbar_inval(sb + SM_EMPTY0);
        mbar_inval(sb + SM_EMPTY1);
    }
    __syncthreads();
    if (warp == 0) {
        asm volatile("tcgen05.dealloc.cta_group::1.sync.aligned.b32 %0, %1;"
                     :: "r"(tmem), "r"(128u));
    }
#else
    // ===================== scalar FFMA2 fallback (compile-only) =====================
    float2* W2p = (float2*)(smem + FB_W2P);
    float*  b1f = (float*)(smem + FB_B1);
    float*  b2f = (float*)(smem + FB_B2);
    for (int p = tid; p < HID * 16; p += THREADS) {
        int h = p >> 4, o2 = p & 15;
        W2p[h * 16 + o2] = make_float2(W2[(2 * o2) * HID + h],
                                       W2[(2 * o2 + 1) * HID + h]);
    }
    if (tid < HID) b1f[tid] = b1[tid];
    if (tid < OUT) b2f[tid] = b2[tid];
    __syncthreads();

    if (tid < 128) {
        const int i  = ibase + (tid >> 4);
        const int jl = tid & 15;
        const float cx = Coords[i * 3 + 0];
        const float cy = Coords[i * 3 + 1];
        const float cz = Coords[i * 3 + 2];
        const float4* Ar = (const float4*)(g_A + i * HID);
        const unsigned w2sm = smem_u32(W2p);

        for (int it = 0; it < JITERS; ++it) {
            const int j = jblk + it * J_TILE + jl;
            float dx = cx - Coords[j * 3 + 0];
            float dy = cy - Coords[j * 3 + 1];
            float dz = cz - Coords[j * 3 + 2];
            float d2 = dx * dx + dy * dy + dz * dz;
            float dist = (d2 > 0.f) ? d2 * rsqrtf(d2) : 0.f;
            const float w = Edges[(size_t)i * N_NODES + j] * dist;

            const float4* Br = (const float4*)(g_B + j * HID);
            unsigned long long acc[16];
#pragma unroll
            for (int o2 = 0; o2 < 16; ++o2) acc[o2] = 0ull;

#pragma unroll 4
            for (int c = 0; c < 16; ++c) {
                float4 a  = __ldg(Ar + c);
                float4 bb = __ldg(Br + c);
                float4 bv = __ldg(((const float4*)b1) + c);
                float av[4] = {a.x, a.y, a.z, a.w};
                float pv[4] = {bb.x, bb.y, bb.z, bb.w};
                float cv[4] = {bv.x, bv.y, bv.z, bv.w};
#pragma unroll
                for (int k = 0; k < 4; ++k) {
                    float g = swish_fast(fmaf(w, av[k] + pv[k], cv[k]));
                    unsigned long long g2 = pack2(g, g);
                    unsigned base = w2sm + (unsigned)(4 * c + k) * (16 * 8);
#pragma unroll
                    for (int o2 = 0; o2 < 16; ++o2) {
                        unsigned long long wv = lds_u64(base + o2 * 8);
                        FFMA2(acc[o2], g2, wv);
                    }
                }
            }

            const size_t orow = ((size_t)i * N_NODES + j) * OUT;
#pragma unroll
            for (int o4 = 0; o4 < 8; ++o4) {
                float a, b, c, d;
                unpack2(acc[2 * o4 + 0], a, b);
                unpack2(acc[2 * o4 + 1], c, d);
                float4 v;
                v.x = swish_fast(a + b2f[4 * o4 + 0]);
                v.y = swish_fast(b + b2f[4 * o4 + 1]);
                v.z = swish_fast(c + b2f[4 * o4 + 2]);
                v.w = swish_fast(d + b2f[4 * o4 + 3]);
                *(float4*)(out + orow + 4 * o4) = v;
            }
        }
    }
#endif
}

// ---------------------------------------------------------------------------
// Harness entry. Inputs: Edges, Coordinates, Embeddings, W1, b1, W2, b2.
// Output: float32 (N, N, OUT).
// ---------------------------------------------------------------------------
extern "C" void kernel_launch(void* const* d_in, const int* in_sizes, int n_in,
                              void* d_out, int out_size) {
    const float* Edges  = (const float*)d_in[0];
    const float* Coords = (const float*)d_in[1];
    const float* Emb    = (const float*)d_in[2];
    const float* W1     = (const float*)d_in[3];
    const float* b1     = (const float*)d_in[4];
    const float* W2     = (const float*)d_in[5];
    const float* b2     = (const float*)d_in[6];
    float* out = (float*)d_out;

    precompute_AB<<<(N_NODES * HID) / 256, 256>>>(Emb, W1);

    dim3 grid(N_NODES / (J_TILE * JITERS), N_NODES / I_TILE);  // (8, 128)
    edge_mlp_tc<<<grid, THREADS, SM_TOTAL>>>(Edges, Coords, b1, W2, b2, out);
}

// round 10
// speedup vs baseline: 1.1720x; 1.0338x over previous
#include <cuda_runtime.h>
#include <cuda_bf16.h>
#include <cuda_fp16.h>
#include <cstdint>
#include <cstddef>

#define N_NODES 1024
#define F_IN    32
#define HID     64
#define OUT     32
#define I_TILE  8
#define J_TILE  16
#define JITERS  8     // j-tiles per block
#define THREADS 256

#if defined(__CUDA_ARCH__) && (defined(__CUDA_ARCH_FEAT_SM103_ALL) || \
                               defined(__CUDA_ARCH_FEAT_SM100_ALL) || \
                               defined(__CUDA_ARCH_FAMILY_SPECIFIC__))
#define USE_TC 1
#else
#define USE_TC 0
#endif

__device__ float g_A[N_NODES * HID];   // A[i,h] = Emb[i,:] . W1[h, :F]
__device__ float g_B[N_NODES * HID];   // B[j,h] = Emb[j,:] . W1[h, F:]

// ---------------------------------------------------------------------------
// Kernel 1: A/B precompute (tiny)
// ---------------------------------------------------------------------------
__global__ void precompute_AB(const float* __restrict__ Emb,
                              const float* __restrict__ W1) {
    int idx = blockIdx.x * blockDim.x + threadIdx.x;
    int i = idx >> 6;
    int h = idx & 63;
    const float* er = Emb + i * F_IN;
    const float* wr = W1 + h * (2 * F_IN);
    float sa = 0.f, sb = 0.f;
#pragma unroll
    for (int f = 0; f < F_IN; ++f) {
        float e = er[f];
        sa = fmaf(e, wr[f], sa);
        sb = fmaf(e, wr[F_IN + f], sb);
    }
    g_A[idx] = sa;
    g_B[idx] = sb;
}

// ---------------------------------------------------------------------------
// Helpers
// ---------------------------------------------------------------------------
__device__ __forceinline__ unsigned smem_u32(const void* p) {
    unsigned a;
    asm("{ .reg .u64 t; cvta.to.shared.u64 t, %1; cvt.u32.u64 %0, t; }"
        : "=r"(a) : "l"(p));
    return a;
}

__device__ __forceinline__ unsigned long long pack2(float lo, float hi) {
    unsigned long long r;
    asm("mov.b64 %0, {%1, %2};"
        : "=l"(r) : "r"(__float_as_uint(lo)), "r"(__float_as_uint(hi)));
    return r;
}

__device__ __forceinline__ void unpack2(unsigned long long v, float& lo, float& hi) {
    unsigned a, b;
    asm("mov.b64 {%0, %1}, %2;" : "=r"(a), "=r"(b) : "l"(v));
    lo = __uint_as_float(a);
    hi = __uint_as_float(b);
}

__device__ __forceinline__ unsigned long long lds_u64(unsigned addr) {
    unsigned long long r;
    asm volatile("ld.shared.b64 %0, [%1];" : "=l"(r) : "r"(addr));
    return r;
}

#define FFMA2(acc, a, b) \
    asm("fma.rn.f32x2 %0, %1, %2, %0;" : "+l"(acc) : "l"(a), "l"(b))

// swish(x) = x*sigmoid(x) = h*(1+tanh(h)), h = x/2.  1 MUFU.
__device__ __forceinline__ float swish_fast(float x) {
    float h = 0.5f * x;
    float t;
    asm("tanh.approx.f32 %0, %1;" : "=f"(t) : "f"(h));
    return fmaf(h, t, h);
}

// pack two f32 -> f16x2 (first arg -> low half)
__device__ __forceinline__ unsigned cvt2f16(float lo, float hi) {
    unsigned r;
    asm("cvt.rn.f16x2.f32 %0, %1, %2;" : "=r"(r) : "f"(hi), "f"(lo));
    return r;
}

#if USE_TC
__device__ __forceinline__ bool elect_one() {
    unsigned pred;
    asm volatile("{\n\t.reg .pred p;\n\telect.sync _|p, 0xFFFFFFFF;\n\t"
                 "selp.b32 %0, 1, 0, p;\n\t}" : "=r"(pred));
    return pred != 0;
}

__device__ __forceinline__ void mbar_init(unsigned addr, unsigned cnt) {
    asm volatile("mbarrier.init.shared.b64 [%0], %1;" :: "r"(addr), "r"(cnt) : "memory");
}

__device__ __forceinline__ void mbar_inval(unsigned addr) {
    asm volatile("mbarrier.inval.shared.b64 [%0];" :: "r"(addr) : "memory");
}

__device__ __forceinline__ void mbar_arrive(unsigned addr) {
    asm volatile("mbarrier.arrive.release.cta.shared::cta.b64 _, [%0];"
                 :: "r"(addr) : "memory");
}

__device__ __forceinline__ void mbar_wait(unsigned addr, unsigned parity) {
    asm volatile(
        "{\n\t.reg .pred P;\n\t"
        "WL_%=:\n\t"
        "mbarrier.try_wait.parity.acquire.cta.shared::cta.b64 P, [%0], %1, 0x989680;\n\t"
        "@P bra.uni WD_%=;\n\t"
        "bra.uni WL_%=;\n\t"
        "WD_%=:\n\t}"
        :: "r"(addr), "r"(parity) : "memory");
}

// SW128 K-major smem descriptor: layout=2, version=1, SBO=64, LBO=1
__device__ __forceinline__ unsigned long long sdesc(unsigned addr) {
    const unsigned long long base =
        (2ull << 61) | (1ull << 46) | (64ull << 32) | (1ull << 16);
    return base | ((unsigned long long)(addr >> 4) & 0x3FFF);
}

// idesc kind::f16: dtype=F32, atype=btype=F16(0), N=32, M=128 -> 0x8080010
#define MMA_IDESC ((1u << 4) | ((OUT / 8) << 17) | (8u << 24))

// TS-form: A operand in TMEM
__device__ __forceinline__ void mma_f16_ts(unsigned d_tmem, unsigned a_tmem,
                                           unsigned long long b_desc,
                                           unsigned en) {
    asm volatile(
        "{\n\t.reg .pred p;\n\t"
        "setp.ne.u32 p, %5, 0;\n\t"
        "tcgen05.mma.cta_group::1.kind::f16 [%0], [%1], %2, %3, {%4, %4, %4, %4}, p;\n\t"
        "}"
        :: "r"(d_tmem), "r"(a_tmem), "l"(b_desc), "r"(MMA_IDESC), "r"(0u), "r"(en)
        : "memory");
}
#endif  // USE_TC

// ---------------------------------------------------------------------------
// Dynamic SMEM layout. Total 21376 B.
// ---------------------------------------------------------------------------
#define SM_TMEM   0
#define SM_FULL0  8
#define SM_FULL1  16
#define SM_EMPTY0 24
#define SM_EMPTY1 32
#define SM_BSF0   40
#define SM_BSF1   48
#define SM_BSE0   56
#define SM_BSE1   64
#define SM_WHI    1024                    // 32 x 64 f16 SW128 = 4KB
#define SM_WLO    (SM_WHI + 4096)         // 5120
#define SM_BS0    (SM_WLO + 4096)         // 9216  (16 rows x 64 f, XOR layout)
#define SM_BS1    (SM_BS0 + 4096)         // 13312
#define SM_AS     (SM_BS1 + 4096)         // 17408 (8 rows x 64 f = 2KB)
#define SM_B1     (SM_AS + 2048)          // 19456
#define SM_B2     (SM_B1 + 256)           // 19712
#define SM_CJ     (SM_B2 + 128)           // 19840 (128 j x 3 f = 1536B)
#define SM_TOTAL  (SM_CJ + 1536)          // 21376

// Fallback layout (front of same buffer)
#define FB_W2P  0
#define FB_B1   (FB_W2P + HID * 16 * 8)
#define FB_B2   (FB_B1 + HID * 4)

#define SWZ(off) ((off) ^ (((off) >> 3) & 0x70))
// Bs addressing: buffer buf, row jl (256B), float4 slot c4 at (c4 ^ jl)*16
#define BS_ADDR(buf, jl, c4) \
    (SM_BS0 + ((unsigned)(buf) << 12) + ((jl) << 8) + ((unsigned)((c4) ^ (jl)) << 4))

// TMEM column offsets (alloc 128 cols)
#define TM_D0 0
#define TM_D1 32
#define TM_A0 64
#define TM_A1 96

// ---------------------------------------------------------------------------
// Kernel 2: warp-specialized fused edge MLP.
// warps 0-3 producers: h1, STTM, MMA, commit.
// warps 4-7 consumers: LDTM, swish, store, AND B-tile staging 2 iters ahead.
// Bs slots synced by BsFull/BsEmpty mbar pairs so B LDG latency is off the
// producer critical path entirely.
// ---------------------------------------------------------------------------
__global__ __launch_bounds__(THREADS, 3)
void edge_mlp_tc(const float* __restrict__ Edges,
                 const float* __restrict__ Coords,
                 const float* __restrict__ b1,
                 const float* __restrict__ W2,
                 const float* __restrict__ b2,
                 float* __restrict__ out) {
    extern __shared__ char smem[];
    const int tid  = threadIdx.x;
    const int warp = tid >> 5;
    const int ibase = blockIdx.y * I_TILE;
    const int jblk  = blockIdx.x * (J_TILE * JITERS);

#if USE_TC
    const unsigned sb = smem_u32(smem);
    if (warp == 0) {
        asm volatile("tcgen05.alloc.cta_group::1.sync.aligned.shared::cta.b32 [%0], %1;"
                     :: "r"(sb + SM_TMEM), "r"(128u) : "memory");
        asm volatile("tcgen05.relinquish_alloc_permit.cta_group::1.sync.aligned;");
    }
    if (tid == 0) {
        mbar_init(sb + SM_FULL0, 1);
        mbar_init(sb + SM_FULL1, 1);
        mbar_init(sb + SM_EMPTY0, 4);   // 4 consumer warps
        mbar_init(sb + SM_EMPTY1, 4);
        mbar_init(sb + SM_BSF0, 4);     // 4 consumer warps (stagers)
        mbar_init(sb + SM_BSF1, 4);
        mbar_init(sb + SM_BSE0, 4);     // 4 producer warps
        mbar_init(sb + SM_BSE1, 4);
    }

    // ---- one-time staging: W2 (fp16 hi/lo, SW128), A rows, b1, b2, Cj ----
    for (int p = tid; p < OUT * 32; p += THREADS) {
        int o = p >> 5, h2 = p & 31;
        float w0 = W2[o * HID + 2 * h2];
        float w1 = W2[o * HID + 2 * h2 + 1];
        unsigned hi = cvt2f16(w0, w1);
        float r0 = w0 - __half2float(__ushort_as_half((unsigned short)(hi & 0xFFFF)));
        float r1 = w1 - __half2float(__ushort_as_half((unsigned short)(hi >> 16)));
        unsigned lo = cvt2f16(r0, r1);
        unsigned sw = SWZ((unsigned)(o * 128 + h2 * 4));
        *(unsigned*)(smem + SM_WHI + sw) = hi;
        *(unsigned*)(smem + SM_WLO + sw) = lo;
    }
    if (tid < 128)
        ((float4*)(smem + SM_AS))[tid] = ((const float4*)(g_A + ibase * HID))[tid];
    if (tid < 16) ((float4*)(smem + SM_B1))[tid] = ((const float4*)b1)[tid];
    else if (tid < 24) ((float4*)(smem + SM_B2))[tid - 16] = ((const float4*)b2)[tid - 16];
    for (int p = tid; p < 3 * J_TILE * JITERS; p += THREADS)
        ((float*)(smem + SM_CJ))[p] = Coords[jblk * 3 + p];

    asm volatile("fence.proxy.async.shared::cta;" ::: "memory");
    __syncthreads();

    unsigned tmem;
    asm("ld.shared.b32 %0, [%1];" : "=r"(tmem) : "r"(sb + SM_TMEM));

    if (tid < 128) {
        // =========================== PRODUCERS ===========================
        const int ptid = tid;
        const int irow = ptid >> 4;
        const int i    = ibase + irow;
        const int jl   = ptid & 15;
        const unsigned warp_off = (unsigned)warp << 21;

        const float cx = Coords[i * 3 + 0];
        const float cy = Coords[i * 3 + 1];
        const float cz = Coords[i * 3 + 2];

        const float4* Asr = (const float4*)(smem + SM_AS + irow * 256);
        const float4* b1s = (const float4*)(smem + SM_B1);
        const float*  CjS = (const float*)(smem + SM_CJ);
        const unsigned long long whiD = sdesc(sb + SM_WHI);
        const unsigned long long wloD = sdesc(sb + SM_WLO);

        const float* erow = Edges + (size_t)i * N_NODES + jblk + jl;
        float epre = __ldg(erow);                   // Edges for t=0

        for (int t = 0; t < JITERS; ++t) {
            const int slot = t & 1;

            float ecur = epre;
            if (t < JITERS - 1) epre = __ldg(erow + (t + 1) * J_TILE);

            const int cjx = (t * J_TILE + jl) * 3;
            float dx = cx - CjS[cjx + 0];
            float dy = cy - CjS[cjx + 1];
            float dz = cz - CjS[cjx + 2];
            float d2 = dx * dx + dy * dy + dz * dz;
            float dist = (d2 > 0.f) ? d2 * rsqrtf(d2) : 0.f;
            const float w = ecur * dist;

            // wait for consumer-staged Bs[slot] (normally already complete)
            mbar_wait(sb + SM_BSF0 + slot * 8, (t >> 1) & 1);

            // h1 = swish(w*(A+B)+b1) -> 32 f16x2 regs
            unsigned v[32];
#pragma unroll
            for (int c = 0; c < 8; ++c) {
                float4 a0 = Asr[2 * c];
                float4 a1 = Asr[2 * c + 1];
                float4 p0 = *(const float4*)(smem + BS_ADDR(slot, jl, 2 * c));
                float4 p1 = *(const float4*)(smem + BS_ADDR(slot, jl, 2 * c + 1));
                float4 q0 = b1s[2 * c];
                float4 q1 = b1s[2 * c + 1];

                float g0 = swish_fast(fmaf(w, a0.x + p0.x, q0.x));
                float g1 = swish_fast(fmaf(w, a0.y + p0.y, q0.y));
                float g2 = swish_fast(fmaf(w, a0.z + p0.z, q0.z));
                float g3 = swish_fast(fmaf(w, a0.w + p0.w, q0.w));
                float g4 = swish_fast(fmaf(w, a1.x + p1.x, q1.x));
                float g5 = swish_fast(fmaf(w, a1.y + p1.y, q1.y));
                float g6 = swish_fast(fmaf(w, a1.z + p1.z, q1.z));
                float g7 = swish_fast(fmaf(w, a1.w + p1.w, q1.w));

                v[4 * c + 0] = cvt2f16(g0, g1);
                v[4 * c + 1] = cvt2f16(g2, g3);
                v[4 * c + 2] = cvt2f16(g4, g5);
                v[4 * c + 3] = cvt2f16(g6, g7);
            }

            // Bs[slot] fully consumed -> release for restaging (tile t+2)
            __syncwarp();
            if ((tid & 31) == 0) mbar_arrive(sb + SM_BSE0 + slot * 8);

            // A[slot] reuse safe only after MMA[t-2] completed
            if (t >= 2) mbar_wait(sb + SM_FULL0 + slot * 8, ((t - 2) >> 1) & 1);

            const unsigned atm = tmem + (slot ? TM_A1 : TM_A0);
            asm volatile(
                "tcgen05.st.sync.aligned.32x32b.x32.b32 [%0], "
                "{%1, %2, %3, %4, %5, %6, %7, %8, "
                " %9, %10, %11, %12, %13, %14, %15, %16, "
                " %17, %18, %19, %20, %21, %22, %23, %24, "
                " %25, %26, %27, %28, %29, %30, %31, %32};"
                :: "r"(atm + warp_off),
                   "r"(v[0]),  "r"(v[1]),  "r"(v[2]),  "r"(v[3]),
                   "r"(v[4]),  "r"(v[5]),  "r"(v[6]),  "r"(v[7]),
                   "r"(v[8]),  "r"(v[9]),  "r"(v[10]), "r"(v[11]),
                   "r"(v[12]), "r"(v[13]), "r"(v[14]), "r"(v[15]),
                   "r"(v[16]), "r"(v[17]), "r"(v[18]), "r"(v[19]),
                   "r"(v[20]), "r"(v[21]), "r"(v[22]), "r"(v[23]),
                   "r"(v[24]), "r"(v[25]), "r"(v[26]), "r"(v[27]),
                   "r"(v[28]), "r"(v[29]), "r"(v[30]), "r"(v[31])
                : "memory");
            asm volatile("tcgen05.wait::st.sync.aligned;" ::: "memory");
            asm volatile("tcgen05.fence::before_thread_sync;" ::: "memory");

            asm volatile("bar.sync 1, 128;" ::: "memory");   // all STTM done

            if (warp == 0 && elect_one()) {
                asm volatile("tcgen05.fence::after_thread_sync;" ::: "memory");
                if (t >= 2) mbar_wait(sb + SM_EMPTY0 + slot * 8, ((t - 2) >> 1) & 1);
                const unsigned dtm = tmem + (slot ? TM_D1 : TM_D0);
                unsigned en = 0;
#pragma unroll
                for (int k = 0; k < 4; ++k) { mma_f16_ts(dtm, atm + k * 8, whiD + 2 * k, en); en = 1; }
#pragma unroll
                for (int k = 0; k < 4; ++k) { mma_f16_ts(dtm, atm + k * 8, wloD + 2 * k, 1); }
                asm volatile(
                    "tcgen05.commit.cta_group::1.mbarrier::arrive::one.shared::cluster.b64 [%0];"
                    :: "r"(sb + SM_FULL0 + (unsigned)slot * 8) : "memory");
            }
        }
    } else {
        // =========================== CONSUMERS ===========================
        const int ctid = tid - 128;
        const int i    = ibase + (ctid >> 4);
        const int jfix = ctid & 15;
        const float4* b2s = (const float4*)(smem + SM_B2);

        // prologue: stage B tiles 0 and 1
#pragma unroll
        for (int u = 0; u < 2; ++u) {
            const float4* src = (const float4*)(g_B + (jblk + u * J_TILE) * HID);
#pragma unroll
            for (int p = ctid; p < 256; p += 128) {
                int jj = p >> 4, c4 = p & 15;
                *(float4*)(smem + BS_ADDR(u, jj, c4)) = src[p];
            }
            __syncwarp();
            if ((tid & 31) == 0) mbar_arrive(sb + SM_BSF0 + u * 8);
        }

        for (int t = 0; t < JITERS; ++t) {
            const int slot = t & 1;
            mbar_wait(sb + SM_FULL0 + slot * 8, (t >> 1) & 1);
            asm volatile("tcgen05.fence::after_thread_sync;" ::: "memory");

            unsigned d[32];
            asm volatile(
                "tcgen05.ld.sync.aligned.32x32b.x32.b32 "
                "{%0, %1, %2, %3, %4, %5, %6, %7, "
                " %8, %9, %10, %11, %12, %13, %14, %15, "
                " %16, %17, %18, %19, %20, %21, %22, %23, "
                " %24, %25, %26, %27, %28, %29, %30, %31}, [%32];"
                : "=r"(d[0]),  "=r"(d[1]),  "=r"(d[2]),  "=r"(d[3]),
                  "=r"(d[4]),  "=r"(d[5]),  "=r"(d[6]),  "=r"(d[7]),
                  "=r"(d[8]),  "=r"(d[9]),  "=r"(d[10]), "=r"(d[11]),
                  "=r"(d[12]), "=r"(d[13]), "=r"(d[14]), "=r"(d[15]),
                  "=r"(d[16]), "=r"(d[17]), "=r"(d[18]), "=r"(d[19]),
                  "=r"(d[20]), "=r"(d[21]), "=r"(d[22]), "=r"(d[23]),
                  "=r"(d[24]), "=r"(d[25]), "=r"(d[26]), "=r"(d[27]),
                  "=r"(d[28]), "=r"(d[29]), "=r"(d[30]), "=r"(d[31])
                : "r"(tmem + (slot ? TM_D1 : TM_D0)));
            asm volatile("tcgen05.wait::ld.sync.aligned;" ::: "memory");
            asm volatile("tcgen05.fence::before_thread_sync;" ::: "memory");

            if ((tid & 31) == 0) mbar_arrive(sb + SM_EMPTY0 + slot * 8);

            // restage Bs[slot] with tile t+2 (producer is ~1 iter behind need)
            if (t < JITERS - 2) {
                mbar_wait(sb + SM_BSE0 + slot * 8, (t >> 1) & 1);
                const float4* src =
                    (const float4*)(g_B + (jblk + (t + 2) * J_TILE) * HID);
#pragma unroll
                for (int p = ctid; p < 256; p += 128) {
                    int jj = p >> 4, c4 = p & 15;
                    *(float4*)(smem + BS_ADDR(slot, jj, c4)) = src[p];
                }
                __syncwarp();
                if ((tid & 31) == 0) mbar_arrive(sb + SM_BSF0 + slot * 8);
            }

            const size_t orow =
                ((size_t)i * N_NODES + (jblk + t * J_TILE + jfix)) * OUT;
#pragma unroll
            for (int q = 0; q < 8; ++q) {
                float4 bq = b2s[q];
                float4 o4;
                o4.x = swish_fast(__uint_as_float(d[4 * q + 0]) + bq.x);
                o4.y = swish_fast(__uint_as_float(d[4 * q + 1]) + bq.y);
                o4.z = swish_fast(__uint_as_float(d[4 * q + 2]) + bq.z);
                o4.w = swish_fast(__uint_as_float(d[4 * q + 3]) + bq.w);
                *(float4*)(out + orow + 4 * q) = o4;
            }
        }
    }

    __syncthreads();
    if (tid == 0) {
        mbar_inval(sb + SM_FULL0);
        mbar_inval(sb + SM_FULL1);
        mbar_inval(sb + SM_EMPTY0);
        mbar_inval(sb + SM_EMPTY1);
        mbar_inval(sb + SM_BSF0);
        mbar_inval(sb + SM_BSF1);
        mbar_inval(sb + SM_BSE0);
        mbar_inval(sb + SM_BSE1);
    }
    __syncthreads();
    if (warp == 0) {
        asm volatile("tcgen05.dealloc.cta_group::1.sync.aligned.b32 %0, %1;"
                     :: "r"(tmem), "r"(128u));
    }
#else
    // ===================== scalar FFMA2 fallback (compile-only) =====================
    float2* W2p = (float2*)(smem + FB_W2P);
    float*  b1f = (float*)(smem + FB_B1);
    float*  b2f = (float*)(smem + FB_B2);
    for (int p = tid; p < HID * 16; p += THREADS) {
        int h = p >> 4, o2 = p & 15;
        W2p[h * 16 + o2] = make_float2(W2[(2 * o2) * HID + h],
                                       W2[(2 * o2 + 1) * HID + h]);
    }
    if (tid < HID) b1f[tid] = b1[tid];
    if (tid < OUT) b2f[tid] = b2[tid];
    __syncthreads();

    if (tid < 128) {
        const int i  = ibase + (tid >> 4);
        const int jl = tid & 15;
        const float cx = Coords[i * 3 + 0];
        const float cy = Coords[i * 3 + 1];
        const float cz = Coords[i * 3 + 2];
        const float4* Ar = (const float4*)(g_A + i * HID);
        const unsigned w2sm = smem_u32(W2p);

        for (int it = 0; it < JITERS; ++it) {
            const int j = jblk + it * J_TILE + jl;
            float dx = cx - Coords[j * 3 + 0];
            float dy = cy - Coords[j * 3 + 1];
            float dz = cz - Coords[j * 3 + 2];
            float d2 = dx * dx + dy * dy + dz * dz;
            float dist = (d2 > 0.f) ? d2 * rsqrtf(d2) : 0.f;
            const float w = Edges[(size_t)i * N_NODES + j] * dist;

            const float4* Br = (const float4*)(g_B + j * HID);
            unsigned long long acc[16];
#pragma unroll
            for (int o2 = 0; o2 < 16; ++o2) acc[o2] = 0ull;

#pragma unroll 4
            for (int c = 0; c < 16; ++c) {
                float4 a  = __ldg(Ar + c);
                float4 bb = __ldg(Br + c);
                float4 bv = __ldg(((const float4*)b1) + c);
                float av[4] = {a.x, a.y, a.z, a.w};
                float pv[4] = {bb.x, bb.y, bb.z, bb.w};
                float cv[4] = {bv.x, bv.y, bv.z, bv.w};
#pragma unroll
                for (int k = 0; k < 4; ++k) {
                    float g = swish_fast(fmaf(w, av[k] + pv[k], cv[k]));
                    unsigned long long g2 = pack2(g, g);
                    unsigned base = w2sm + (unsigned)(4 * c + k) * (16 * 8);
#pragma unroll
                    for (int o2 = 0; o2 < 16; ++o2) {
                        unsigned long long wv = lds_u64(base + o2 * 8);
                        FFMA2(acc[o2], g2, wv);
                    }
                }
            }

            const size_t orow = ((size_t)i * N_NODES + j) * OUT;
#pragma unroll
            for (int o4 = 0; o4 < 8; ++o4) {
                float a, b, c, d;
                unpack2(acc[2 * o4 + 0], a, b);
                unpack2(acc[2 * o4 + 1], c, d);
                float4 v;
                v.x = swish_fast(a + b2f[4 * o4 + 0]);
                v.y = swish_fast(b + b2f[4 * o4 + 1]);
                v.z = swish_fast(c + b2f[4 * o4 + 2]);
                v.w = swish_fast(d + b2f[4 * o4 + 3]);
                *(float4*)(out + orow + 4 * o4) = v;
            }
        }
    }
#endif
}

// ---------------------------------------------------------------------------
// Harness entry. Inputs: Edges, Coordinates, Embeddings, W1, b1, W2, b2.
// Output: float32 (N, N, OUT).
// ---------------------------------------------------------------------------
extern "C" void kernel_launch(void* const* d_in, const int* in_sizes, int n_in,
                              void* d_out, int out_size) {
    const float* Edges  = (const float*)d_in[0];
    const float* Coords = (const float*)d_in[1];
    const float* Emb    = (const float*)d_in[2];
    const float* W1     = (const float*)d_in[3];
    const float* b1     = (const float*)d_in[4];
    const float* W2     = (const float*)d_in[5];
    const float* b2     = (const float*)d_in[6];
    float* out = (float*)d_out;

    precompute_AB<<<(N_NODES * HID) / 256, 256>>>(Emb, W1);

    dim3 grid(N_NODES / (J_TILE * JITERS), N_NODES / I_TILE);  // (8, 128)
    edge_mlp_tc<<<grid, THREADS, SM_TOTAL>>>(Edges, Coords, b1, W2, b2, out);
}

// round 11
// speedup vs baseline: 1.3006x; 1.1097x over previous
#include <cuda_runtime.h>
#include <cuda_bf16.h>
#include <cuda_fp16.h>
#include <cstdint>
#include <cstddef>

#define N_NODES 1024
#define F_IN    32
#define HID     64
#define OUT     32
#define I_TILE  8
#define J_TILE  16
#define JITERS  8     // j-tiles per block
#define THREADS 256

#if defined(__CUDA_ARCH__) && (defined(__CUDA_ARCH_FEAT_SM103_ALL) || \
                               defined(__CUDA_ARCH_FEAT_SM100_ALL) || \
                               defined(__CUDA_ARCH_FAMILY_SPECIFIC__))
#define USE_TC 1
#else
#define USE_TC 0
#endif

__device__ float g_A[N_NODES * HID];   // A[i,h] = Emb[i,:] . W1[h, :F]
__device__ float g_B[N_NODES * HID];   // B[j,h] = Emb[j,:] . W1[h, F:]

// ---------------------------------------------------------------------------
// Kernel 1: A/B precompute — smem-staged W1 (padded, conflict-free), emb
// broadcast, coalesced stores. 256 blocks x 256 thr; block = 4 i-rows.
// ---------------------------------------------------------------------------
__global__ __launch_bounds__(256)
void precompute_AB(const float* __restrict__ Emb,
                   const float* __restrict__ W1) {
    __shared__ float w1s[HID][2 * F_IN + 1];   // [64][65] pad -> bank=(h+f)&31
    __shared__ float embs[4][F_IN + 1];
    const int tid = threadIdx.x;
    const int ibase = blockIdx.x * 4;

    for (int p = tid; p < HID * 2 * F_IN; p += 256) {
        int r = p >> 6, c = p & 63;
        w1s[r][c] = W1[p];
    }
    if (tid < 4 * F_IN)
        embs[tid >> 5][tid & 31] = Emb[ibase * F_IN + tid];
    __syncthreads();

    const int il = tid >> 6;      // 0..3 (broadcast within warp)
    const int h  = tid & 63;
    float sa = 0.f, sb = 0.f;
#pragma unroll
    for (int f = 0; f < F_IN; ++f) {
        float e = embs[il][f];
        sa = fmaf(e, w1s[h][f], sa);
        sb = fmaf(e, w1s[h][F_IN + f], sb);
    }
    const int idx = (ibase + il) * HID + h;   // consecutive tid -> coalesced
    g_A[idx] = sa;
    g_B[idx] = sb;
}

// ---------------------------------------------------------------------------
// Helpers
// ---------------------------------------------------------------------------
__device__ __forceinline__ unsigned smem_u32(const void* p) {
    unsigned a;
    asm("{ .reg .u64 t; cvta.to.shared.u64 t, %1; cvt.u32.u64 %0, t; }"
        : "=r"(a) : "l"(p));
    return a;
}

__device__ __forceinline__ unsigned long long pack2(float lo, float hi) {
    unsigned long long r;
    asm("mov.b64 %0, {%1, %2};"
        : "=l"(r) : "r"(__float_as_uint(lo)), "r"(__float_as_uint(hi)));
    return r;
}

__device__ __forceinline__ void unpack2(unsigned long long v, float& lo, float& hi) {
    unsigned a, b;
    asm("mov.b64 {%0, %1}, %2;" : "=r"(a), "=r"(b) : "l"(v));
    lo = __uint_as_float(a);
    hi = __uint_as_float(b);
}

__device__ __forceinline__ unsigned long long lds_u64(unsigned addr) {
    unsigned long long r;
    asm volatile("ld.shared.b64 %0, [%1];" : "=l"(r) : "r"(addr));
    return r;
}

#define FFMA2(acc, a, b) \
    asm("fma.rn.f32x2 %0, %1, %2, %0;" : "+l"(acc) : "l"(a), "l"(b))

__device__ __forceinline__ float tanh_f(float x) {
    float t;
    asm("tanh.approx.f32 %0, %1;" : "=f"(t) : "f"(x));
    return t;
}

// swish(x) for the fallback path (full form)
__device__ __forceinline__ float swish_fast(float x) {
    float h = 0.5f * x;
    float t = tanh_f(h);
    return fmaf(h, t, h);
}

// Given h = x/2 already: swish(x) = h*(1+tanh(h))
__device__ __forceinline__ float swish_from_half(float h) {
    float t = tanh_f(h);
    return fmaf(h, t, h);
}

// pack two f32 -> f16x2 (first arg -> low half)
__device__ __forceinline__ unsigned cvt2f16(float lo, float hi) {
    unsigned r;
    asm("cvt.rn.f16x2.f32 %0, %1, %2;" : "=r"(r) : "f"(hi), "f"(lo));
    return r;
}

#if USE_TC
__device__ __forceinline__ bool elect_one() {
    unsigned pred;
    asm volatile("{\n\t.reg .pred p;\n\telect.sync _|p, 0xFFFFFFFF;\n\t"
                 "selp.b32 %0, 1, 0, p;\n\t}" : "=r"(pred));
    return pred != 0;
}

__device__ __forceinline__ void mbar_init(unsigned addr, unsigned cnt) {
    asm volatile("mbarrier.init.shared.b64 [%0], %1;" :: "r"(addr), "r"(cnt) : "memory");
}

__device__ __forceinline__ void mbar_inval(unsigned addr) {
    asm volatile("mbarrier.inval.shared.b64 [%0];" :: "r"(addr) : "memory");
}

__device__ __forceinline__ void mbar_arrive(unsigned addr) {
    asm volatile("mbarrier.arrive.release.cta.shared::cta.b64 _, [%0];"
                 :: "r"(addr) : "memory");
}

__device__ __forceinline__ void mbar_wait(unsigned addr, unsigned parity) {
    asm volatile(
        "{\n\t.reg .pred P;\n\t"
        "WL_%=:\n\t"
        "mbarrier.try_wait.parity.acquire.cta.shared::cta.b64 P, [%0], %1, 0x989680;\n\t"
        "@P bra.uni WD_%=;\n\t"
        "bra.uni WL_%=;\n\t"
        "WD_%=:\n\t}"
        :: "r"(addr), "r"(parity) : "memory");
}

// SW128 K-major smem descriptor: layout=2, version=1, SBO=64, LBO=1
__device__ __forceinline__ unsigned long long sdesc(unsigned addr) {
    const unsigned long long base =
        (2ull << 61) | (1ull << 46) | (64ull << 32) | (1ull << 16);
    return base | ((unsigned long long)(addr >> 4) & 0x3FFF);
}

// idesc kind::f16: dtype=F32, atype=btype=F16(0), N=32, M=128 -> 0x8080010
#define MMA_IDESC ((1u << 4) | ((OUT / 8) << 17) | (8u << 24))

// TS-form: A operand in TMEM
__device__ __forceinline__ void mma_f16_ts(unsigned d_tmem, unsigned a_tmem,
                                           unsigned long long b_desc,
                                           unsigned en) {
    asm volatile(
        "{\n\t.reg .pred p;\n\t"
        "setp.ne.u32 p, %5, 0;\n\t"
        "tcgen05.mma.cta_group::1.kind::f16 [%0], [%1], %2, %3, {%4, %4, %4, %4}, p;\n\t"
        "}"
        :: "r"(d_tmem), "r"(a_tmem), "l"(b_desc), "r"(MMA_IDESC), "r"(0u), "r"(en)
        : "memory");
}
#endif  // USE_TC

// ---------------------------------------------------------------------------
// Dynamic SMEM layout. Total 21376 B.
// ---------------------------------------------------------------------------
#define SM_TMEM   0
#define SM_FULL0  8
#define SM_FULL1  16
#define SM_EMPTY0 24
#define SM_EMPTY1 32
#define SM_BSF0   40
#define SM_BSF1   48
#define SM_BSE0   56
#define SM_BSE1   64
#define SM_WHI    1024                    // 32 x 64 f16 SW128 = 4KB
#define SM_WLO    (SM_WHI + 4096)         // 5120
#define SM_BS0    (SM_WLO + 4096)         // 9216  (16 rows x 64 f, XOR layout)
#define SM_BS1    (SM_BS0 + 4096)         // 13312
#define SM_AS     (SM_BS1 + 4096)         // 17408 (8 rows x 64 f = 2KB)
#define SM_B1     (SM_AS + 2048)          // 19456 (0.5*b1)
#define SM_B2     (SM_B1 + 256)           // 19712 (0.5*b2)
#define SM_CJ     (SM_B2 + 128)           // 19840 (128 j x 3 f = 1536B)
#define SM_TOTAL  (SM_CJ + 1536)          // 21376

// Fallback layout (front of same buffer)
#define FB_W2P  0
#define FB_B1   (FB_W2P + HID * 16 * 8)
#define FB_B2   (FB_B1 + HID * 4)

#define SWZ(off) ((off) ^ (((off) >> 3) & 0x70))
// Bs addressing: buffer buf, row jl (256B), float4 slot c4 at (c4 ^ jl)*16
#define BS_ADDR(buf, jl, c4) \
    (SM_BS0 + ((unsigned)(buf) << 12) + ((jl) << 8) + ((unsigned)((c4) ^ (jl)) << 4))

// TMEM column offsets (alloc 128 cols)
#define TM_D0 0
#define TM_D1 32
#define TM_A0 64
#define TM_A1 96

// ---------------------------------------------------------------------------
// Kernel 2: warp-specialized fused edge MLP.
// warps 0-3 producers: h1, STTM, MMA, commit.
// warps 4-7 consumers: LDTM, swish, store, + B-tile staging 2 iters ahead.
// Swish 0.5-factor folded into staged b1/b2 and the edge weight.
// ---------------------------------------------------------------------------
__global__ __launch_bounds__(THREADS, 3)
void edge_mlp_tc(const float* __restrict__ Edges,
                 const float* __restrict__ Coords,
                 const float* __restrict__ b1,
                 const float* __restrict__ W2,
                 const float* __restrict__ b2,
                 float* __restrict__ out) {
    extern __shared__ char smem[];
    const int tid  = threadIdx.x;
    const int warp = tid >> 5;
    const int ibase = blockIdx.y * I_TILE;
    const int jblk  = blockIdx.x * (J_TILE * JITERS);

#if USE_TC
    const unsigned sb = smem_u32(smem);
    if (warp == 0) {
        asm volatile("tcgen05.alloc.cta_group::1.sync.aligned.shared::cta.b32 [%0], %1;"
                     :: "r"(sb + SM_TMEM), "r"(128u) : "memory");
        asm volatile("tcgen05.relinquish_alloc_permit.cta_group::1.sync.aligned;");
    }
    if (tid == 0) {
        mbar_init(sb + SM_FULL0, 1);
        mbar_init(sb + SM_FULL1, 1);
        mbar_init(sb + SM_EMPTY0, 4);   // 4 consumer warps
        mbar_init(sb + SM_EMPTY1, 4);
        mbar_init(sb + SM_BSF0, 4);     // 4 consumer warps (stagers)
        mbar_init(sb + SM_BSF1, 4);
        mbar_init(sb + SM_BSE0, 4);     // 4 producer warps
        mbar_init(sb + SM_BSE1, 4);
    }

    // ---- one-time staging: W2 (fp16 hi/lo, SW128), A rows, 0.5*b1/b2, Cj ----
    for (int p = tid; p < OUT * 32; p += THREADS) {
        int o = p >> 5, h2 = p & 31;
        float w0 = W2[o * HID + 2 * h2];
        float w1 = W2[o * HID + 2 * h2 + 1];
        unsigned hi = cvt2f16(w0, w1);
        float r0 = w0 - __half2float(__ushort_as_half((unsigned short)(hi & 0xFFFF)));
        float r1 = w1 - __half2float(__ushort_as_half((unsigned short)(hi >> 16)));
        unsigned lo = cvt2f16(r0, r1);
        unsigned sw = SWZ((unsigned)(o * 128 + h2 * 4));
        *(unsigned*)(smem + SM_WHI + sw) = hi;
        *(unsigned*)(smem + SM_WLO + sw) = lo;
    }
    if (tid < 128)
        ((float4*)(smem + SM_AS))[tid] = ((const float4*)(g_A + ibase * HID))[tid];
    if (tid < HID) ((float*)(smem + SM_B1))[tid] = 0.5f * b1[tid];
    else if (tid < HID + OUT) ((float*)(smem + SM_B2))[tid - HID] = 0.5f * b2[tid - HID];
    for (int p = tid; p < 3 * J_TILE * JITERS; p += THREADS)
        ((float*)(smem + SM_CJ))[p] = Coords[jblk * 3 + p];

    asm volatile("fence.proxy.async.shared::cta;" ::: "memory");
    __syncthreads();

    unsigned tmem;
    asm("ld.shared.b32 %0, [%1];" : "=r"(tmem) : "r"(sb + SM_TMEM));

    if (tid < 128) {
        // =========================== PRODUCERS ===========================
        const int ptid = tid;
        const int irow = ptid >> 4;
        const int i    = ibase + irow;
        const int jl   = ptid & 15;
        const unsigned warp_off = (unsigned)warp << 21;

        const float cx = Coords[i * 3 + 0];
        const float cy = Coords[i * 3 + 1];
        const float cz = Coords[i * 3 + 2];

        const float4* Asr = (const float4*)(smem + SM_AS + irow * 256);
        const float4* b1s = (const float4*)(smem + SM_B1);   // pre-halved
        const float*  CjS = (const float*)(smem + SM_CJ);
        const unsigned long long whiD = sdesc(sb + SM_WHI);
        const unsigned long long wloD = sdesc(sb + SM_WLO);

        const float* erow = Edges + (size_t)i * N_NODES + jblk + jl;
        float epre = __ldg(erow);                   // Edges for t=0

        for (int t = 0; t < JITERS; ++t) {
            const int slot = t & 1;

            float ecur = epre;
            if (t < JITERS - 1) epre = __ldg(erow + (t + 1) * J_TILE);

            const int cjx = (t * J_TILE + jl) * 3;
            float dx = cx - CjS[cjx + 0];
            float dy = cy - CjS[cjx + 1];
            float dz = cz - CjS[cjx + 2];
            float d2 = dx * dx + dy * dy + dz * dz;
            float dist = (d2 > 0.f) ? d2 * rsqrtf(d2) : 0.f;
            const float wh = 0.5f * ecur * dist;    // 0.5 folded in

            // wait for consumer-staged Bs[slot] (normally already complete)
            mbar_wait(sb + SM_BSF0 + slot * 8, (t >> 1) & 1);

            // x = 0.5*pre1; h1 = x*(1+tanh(x)) -> 32 f16x2 regs
            unsigned v[32];
#pragma unroll
            for (int c = 0; c < 8; ++c) {
                float4 a0 = Asr[2 * c];
                float4 a1 = Asr[2 * c + 1];
                float4 p0 = *(const float4*)(smem + BS_ADDR(slot, jl, 2 * c));
                float4 p1 = *(const float4*)(smem + BS_ADDR(slot, jl, 2 * c + 1));
                float4 q0 = b1s[2 * c];
                float4 q1 = b1s[2 * c + 1];

                float g0 = swish_from_half(fmaf(wh, a0.x + p0.x, q0.x));
                float g1 = swish_from_half(fmaf(wh, a0.y + p0.y, q0.y));
                float g2 = swish_from_half(fmaf(wh, a0.z + p0.z, q0.z));
                float g3 = swish_from_half(fmaf(wh, a0.w + p0.w, q0.w));
                float g4 = swish_from_half(fmaf(wh, a1.x + p1.x, q1.x));
                float g5 = swish_from_half(fmaf(wh, a1.y + p1.y, q1.y));
                float g6 = swish_from_half(fmaf(wh, a1.z + p1.z, q1.z));
                float g7 = swish_from_half(fmaf(wh, a1.w + p1.w, q1.w));

                v[4 * c + 0] = cvt2f16(g0, g1);
                v[4 * c + 1] = cvt2f16(g2, g3);
                v[4 * c + 2] = cvt2f16(g4, g5);
                v[4 * c + 3] = cvt2f16(g6, g7);
            }

            // Bs[slot] fully consumed -> release for restaging (tile t+2)
            __syncwarp();
            if ((tid & 31) == 0) mbar_arrive(sb + SM_BSE0 + slot * 8);

            // A[slot] reuse safe only after MMA[t-2] completed
            if (t >= 2) mbar_wait(sb + SM_FULL0 + slot * 8, ((t - 2) >> 1) & 1);

            const unsigned atm = tmem + (slot ? TM_A1 : TM_A0);
            asm volatile(
                "tcgen05.st.sync.aligned.32x32b.x32.b32 [%0], "
                "{%1, %2, %3, %4, %5, %6, %7, %8, "
                " %9, %10, %11, %12, %13, %14, %15, %16, "
                " %17, %18, %19, %20, %21, %22, %23, %24, "
                " %25, %26, %27, %28, %29, %30, %31, %32};"
                :: "r"(atm + warp_off),
                   "r"(v[0]),  "r"(v[1]),  "r"(v[2]),  "r"(v[3]),
                   "r"(v[4]),  "r"(v[5]),  "r"(v[6]),  "r"(v[7]),
                   "r"(v[8]),  "r"(v[9]),  "r"(v[10]), "r"(v[11]),
                   "r"(v[12]), "r"(v[13]), "r"(v[14]), "r"(v[15]),
                   "r"(v[16]), "r"(v[17]), "r"(v[18]), "r"(v[19]),
                   "r"(v[20]), "r"(v[21]), "r"(v[22]), "r"(v[23]),
                   "r"(v[24]), "r"(v[25]), "r"(v[26]), "r"(v[27]),
                   "r"(v[28]), "r"(v[29]), "r"(v[30]), "r"(v[31])
                : "memory");
            asm volatile("tcgen05.wait::st.sync.aligned;" ::: "memory");
            asm volatile("tcgen05.fence::before_thread_sync;" ::: "memory");

            asm volatile("bar.sync 1, 128;" ::: "memory");   // all STTM done

            if (warp == 0 && elect_one()) {
                asm volatile("tcgen05.fence::after_thread_sync;" ::: "memory");
                if (t >= 2) mbar_wait(sb + SM_EMPTY0 + slot * 8, ((t - 2) >> 1) & 1);
                const unsigned dtm = tmem + (slot ? TM_D1 : TM_D0);
                unsigned en = 0;
#pragma unroll
                for (int k = 0; k < 4; ++k) { mma_f16_ts(dtm, atm + k * 8, whiD + 2 * k, en); en = 1; }
#pragma unroll
                for (int k = 0; k < 4; ++k) { mma_f16_ts(dtm, atm + k * 8, wloD + 2 * k, 1); }
                asm volatile(
                    "tcgen05.commit.cta_group::1.mbarrier::arrive::one.shared::cluster.b64 [%0];"
                    :: "r"(sb + SM_FULL0 + (unsigned)slot * 8) : "memory");
            }
        }
    } else {
        // =========================== CONSUMERS ===========================
        const int ctid = tid - 128;
        const int i    = ibase + (ctid >> 4);
        const int jfix = ctid & 15;
        const float4* b2s = (const float4*)(smem + SM_B2);   // pre-halved

        // prologue: stage B tiles 0 and 1
#pragma unroll
        for (int u = 0; u < 2; ++u) {
            const float4* src = (const float4*)(g_B + (jblk + u * J_TILE) * HID);
#pragma unroll
            for (int p = ctid; p < 256; p += 128) {
                int jj = p >> 4, c4 = p & 15;
                *(float4*)(smem + BS_ADDR(u, jj, c4)) = src[p];
            }
            __syncwarp();
            if ((tid & 31) == 0) mbar_arrive(sb + SM_BSF0 + u * 8);
        }

        for (int t = 0; t < JITERS; ++t) {
            const int slot = t & 1;
            mbar_wait(sb + SM_FULL0 + slot * 8, (t >> 1) & 1);
            asm volatile("tcgen05.fence::after_thread_sync;" ::: "memory");

            unsigned d[32];
            asm volatile(
                "tcgen05.ld.sync.aligned.32x32b.x32.b32 "
                "{%0, %1, %2, %3, %4, %5, %6, %7, "
                " %8, %9, %10, %11, %12, %13, %14, %15, "
                " %16, %17, %18, %19, %20, %21, %22, %23, "
                " %24, %25, %26, %27, %28, %29, %30, %31}, [%32];"
                : "=r"(d[0]),  "=r"(d[1]),  "=r"(d[2]),  "=r"(d[3]),
                  "=r"(d[4]),  "=r"(d[5]),  "=r"(d[6]),  "=r"(d[7]),
                  "=r"(d[8]),  "=r"(d[9]),  "=r"(d[10]), "=r"(d[11]),
                  "=r"(d[12]), "=r"(d[13]), "=r"(d[14]), "=r"(d[15]),
                  "=r"(d[16]), "=r"(d[17]), "=r"(d[18]), "=r"(d[19]),
                  "=r"(d[20]), "=r"(d[21]), "=r"(d[22]), "=r"(d[23]),
                  "=r"(d[24]), "=r"(d[25]), "=r"(d[26]), "=r"(d[27]),
                  "=r"(d[28]), "=r"(d[29]), "=r"(d[30]), "=r"(d[31])
                : "r"(tmem + (slot ? TM_D1 : TM_D0)));
            asm volatile("tcgen05.wait::ld.sync.aligned;" ::: "memory");
            asm volatile("tcgen05.fence::before_thread_sync;" ::: "memory");

            if ((tid & 31) == 0) mbar_arrive(sb + SM_EMPTY0 + slot * 8);

            // restage Bs[slot] with tile t+2 (producer is ~1 iter behind need)
            if (t < JITERS - 2) {
                mbar_wait(sb + SM_BSE0 + slot * 8, (t >> 1) & 1);
                const float4* src =
                    (const float4*)(g_B + (jblk + (t + 2) * J_TILE) * HID);
#pragma unroll
                for (int p = ctid; p < 256; p += 128) {
                    int jj = p >> 4, c4 = p & 15;
                    *(float4*)(smem + BS_ADDR(slot, jj, c4)) = src[p];
                }
                __syncwarp();
                if ((tid & 31) == 0) mbar_arrive(sb + SM_BSF0 + slot * 8);
            }

            const size_t orow =
                ((size_t)i * N_NODES + (jblk + t * J_TILE + jfix)) * OUT;
#pragma unroll
            for (int q = 0; q < 8; ++q) {
                float4 bq = b2s[q];                       // 0.5*b2
                float h0 = fmaf(__uint_as_float(d[4 * q + 0]), 0.5f, bq.x);
                float h1 = fmaf(__uint_as_float(d[4 * q + 1]), 0.5f, bq.y);
                float h2 = fmaf(__uint_as_float(d[4 * q + 2]), 0.5f, bq.z);
                float h3 = fmaf(__uint_as_float(d[4 * q + 3]), 0.5f, bq.w);
                float4 o4;
                o4.x = swish_from_half(h0);
                o4.y = swish_from_half(h1);
                o4.z = swish_from_half(h2);
                o4.w = swish_from_half(h3);
                *(float4*)(out + orow + 4 * q) = o4;
            }
        }
    }

    __syncthreads();
    if (tid == 0) {
        mbar_inval(sb + SM_FULL0);
        mbar_inval(sb + SM_FULL1);
        mbar_inval(sb + SM_EMPTY0);
        mbar_inval(sb + SM_EMPTY1);
        mbar_inval(sb + SM_BSF0);
        mbar_inval(sb + SM_BSF1);
        mbar_inval(sb + SM_BSE0);
        mbar_inval(sb + SM_BSE1);
    }
    __syncthreads();
    if (warp == 0) {
        asm volatile("tcgen05.dealloc.cta_group::1.sync.aligned.b32 %0, %1;"
                     :: "r"(tmem), "r"(128u));
    }
#else
    // ===================== scalar FFMA2 fallback (compile-only) =====================
    float2* W2p = (float2*)(smem + FB_W2P);
    float*  b1f = (float*)(smem + FB_B1);
    float*  b2f = (float*)(smem + FB_B2);
    for (int p = tid; p < HID * 16; p += THREADS) {
        int h = p >> 4, o2 = p & 15;
        W2p[h * 16 + o2] = make_float2(W2[(2 * o2) * HID + h],
                                       W2[(2 * o2 + 1) * HID + h]);
    }
    if (tid < HID) b1f[tid] = b1[tid];
    if (tid < OUT) b2f[tid] = b2[tid];
    __syncthreads();

    if (tid < 128) {
        const int i  = ibase + (tid >> 4);
        const int jl = tid & 15;
        const float cx = Coords[i * 3 + 0];
        const float cy = Coords[i * 3 + 1];
        const float cz = Coords[i * 3 + 2];
        const float4* Ar = (const float4*)(g_A + i * HID);
        const unsigned w2sm = smem_u32(W2p);

        for (int it = 0; it < JITERS; ++it) {
            const int j = jblk + it * J_TILE + jl;
            float dx = cx - Coords[j * 3 + 0];
            float dy = cy - Coords[j * 3 + 1];
            float dz = cz - Coords[j * 3 + 2];
            float d2 = dx * dx + dy * dy + dz * dz;
            float dist = (d2 > 0.f) ? d2 * rsqrtf(d2) : 0.f;
            const float w = Edges[(size_t)i * N_NODES + j] * dist;

            const float4* Br = (const float4*)(g_B + j * HID);
            unsigned long long acc[16];
#pragma unroll
            for (int o2 = 0; o2 < 16; ++o2) acc[o2] = 0ull;

#pragma unroll 4
            for (int c = 0; c < 16; ++c) {
                float4 a  = __ldg(Ar + c);
                float4 bb = __ldg(Br + c);
                float4 bv = __ldg(((const float4*)b1) + c);
                float av[4] = {a.x, a.y, a.z, a.w};
                float pv[4] = {bb.x, bb.y, bb.z, bb.w};
                float cv[4] = {bv.x, bv.y, bv.z, bv.w};
#pragma unroll
                for (int k = 0; k < 4; ++k) {
                    float g = swish_fast(fmaf(w, av[k] + pv[k], cv[k]));
                    unsigned long long g2 = pack2(g, g);
                    unsigned base = w2sm + (unsigned)(4 * c + k) * (16 * 8);
#pragma unroll
                    for (int o2 = 0; o2 < 16; ++o2) {
                        unsigned long long wv = lds_u64(base + o2 * 8);
                        FFMA2(acc[o2], g2, wv);
                    }
                }
            }

            const size_t orow = ((size_t)i * N_NODES + j) * OUT;
#pragma unroll
            for (int o4 = 0; o4 < 8; ++o4) {
                float a, b, c, d;
                unpack2(acc[2 * o4 + 0], a, b);
                unpack2(acc[2 * o4 + 1], c, d);
                float4 v;
                v.x = swish_fast(a + b2f[4 * o4 + 0]);
                v.y = swish_fast(b + b2f[4 * o4 + 1]);
                v.z = swish_fast(c + b2f[4 * o4 + 2]);
                v.w = swish_fast(d + b2f[4 * o4 + 3]);
                *(float4*)(out + orow + 4 * o4) = v;
            }
        }
    }
#endif
}

// ---------------------------------------------------------------------------
// Harness entry. Inputs: Edges, Coordinates, Embeddings, W1, b1, W2, b2.
// Output: float32 (N, N, OUT).
// ---------------------------------------------------------------------------
extern "C" void kernel_launch(void* const* d_in, const int* in_sizes, int n_in,
                              void* d_out, int out_size) {
    const float* Edges  = (const float*)d_in[0];
    const float* Coords = (const float*)d_in[1];
    const float* Emb    = (const float*)d_in[2];
    const float* W1     = (const float*)d_in[3];
    const float* b1     = (const float*)d_in[4];
    const float* W2     = (const float*)d_in[5];
    const float* b2     = (const float*)d_in[6];
    float* out = (float*)d_out;

    precompute_AB<<<N_NODES / 4, 256>>>(Emb, W1);

    dim3 grid(N_NODES / (J_TILE * JITERS), N_NODES / I_TILE);  // (8, 128)
    edge_mlp_tc<<<grid, THREADS, SM_TOTAL>>>(Edges, Coords, b1, W2, b2, out);
}